// round 7
// baseline (speedup 1.0000x reference)
#include <cuda_runtime.h>

// ---------------------------------------------------------------------------
// RNNSent: 2-layer LSTM (T=300 steps after the .view trick), B=1024, NHID=256
// Round 3: packed fp32x2 FFMA2 mainloop (exact fp32, 2 FMA/issue) + K-tile 32.
// Outputs: decoded.T [2,1024] ++ h [2,1024,256] ++ c [2,1024,256]  (fp32)
// ---------------------------------------------------------------------------

#define Bsz   1024
#define Tst   300
#define NH    256
#define NG    1024        // 4*NH gate rows
#define KX    32          // padded layer0 input dim (25 -> 32)
#define GSIZE 8           // CTAs per batch-group (hidden split 256/32)
#define NGRP  16          // batch groups (1024/64)
#define NCTA  128

// -------------------- device scratch (static, no allocations) --------------
__device__ float g_X[(size_t)Tst * Bsz * KX];              // [t][b][kx] padded emb
// rows: [0,32)=Wih0T, [32,288)=Whh0T, [288,544)=Wih1T, [544,800)=Whh1T
// col' = hi*128 + g*32 + j  for gate row r = g*256 + hi*32 + j
__device__ float g_WT[(size_t)(KX + 3 * NH) * NG];
__device__ float g_bias[2 * NG];                            // permuted b_ih+b_hh
__device__ float g_H0[2 * Bsz * NH];                        // double-buffered h, layer0
__device__ float g_H1[2 * Bsz * NH];                        // layer1
__device__ unsigned g_bar_count[NGRP];
__device__ unsigned g_bar_gen[NGRP];

// -------------------- packed f32x2 helpers ----------------------------------
__device__ __forceinline__ unsigned long long dup2(float w) {
    unsigned long long r;
    asm("mov.b64 %0, {%1, %1};" : "=l"(r) : "f"(w));
    return r;
}
__device__ __forceinline__ void ffma2(unsigned long long& d, unsigned long long a,
                                      unsigned long long b) {
    asm("fma.rn.f32x2 %0, %1, %2, %0;" : "+l"(d) : "l"(a), "l"(b));
}
__device__ __forceinline__ float2 unpack2(unsigned long long v) {
    float2 f;
    asm("mov.b64 {%0, %1}, %2;" : "=f"(f.x), "=f"(f.y) : "l"(v));
    return f;
}

// -------------------- kernel 1: embedding gather + pad ---------------------
__global__ void gather_emb_kernel(const int* __restrict__ input,
                                  const float* __restrict__ emb) {
    long idx = (long)blockIdx.x * blockDim.x + threadIdx.x;
    long total = (long)Tst * Bsz * KX;
    if (idx >= total) return;
    int k = (int)(idx & (KX - 1));
    long tb = idx >> 5;
    int b = (int)(tb & (Bsz - 1));
    int t = (int)(tb >> 10);
    float v = 0.f;
    if (k < 25) {
        long flat = (long)t * (Bsz * 25) + b * 25 + k;
        int s  = (int)(flat / (Bsz * 300));
        int rr = (int)(flat % (Bsz * 300));
        int bb = rr / 300;
        int e  = rr % 300;
        int tok = input[bb * 25 + s];
        v = emb[(long)tok * 300 + e];
    }
    g_X[idx] = v;
}

// -------------------- kernel 2: weight transpose + permute -----------------
__global__ void prep_weights_kernel(
    const float* __restrict__ Wih0, const float* __restrict__ Whh0,
    const float* __restrict__ bih0, const float* __restrict__ bhh0,
    const float* __restrict__ Wih1, const float* __restrict__ Whh1,
    const float* __restrict__ bih1, const float* __restrict__ bhh1) {
    int idx = blockIdx.x * blockDim.x + threadIdx.x;
    const int total = (KX + 3 * NH) * NG;   // 819200
    if (idx < total) {
        int row  = idx >> 10;
        int colp = idx & 1023;
        int hi = colp >> 7, g = (colp >> 5) & 3, j = colp & 31;
        int r = g * 256 + hi * 32 + j;      // original gate row
        float v;
        if (row < KX)               { int k = row;               v = (k < 25) ? Wih0[r * 25 + k] : 0.f; }
        else if (row < KX + NH)     { int k = row - KX;          v = Whh0[r * 256 + k]; }
        else if (row < KX + 2 * NH) { int k = row - (KX + NH);   v = Wih1[r * 256 + k]; }
        else                        { int k = row - (KX + 2*NH); v = Whh1[r * 256 + k]; }
        g_WT[idx] = v;
    } else if (idx < total + 2 * NG) {
        int i2 = idx - total;
        int l = i2 >> 10, colp = i2 & 1023;
        int hi = colp >> 7, g = (colp >> 5) & 3, j = colp & 31;
        int r = g * 256 + hi * 32 + j;
        g_bias[i2] = (l == 0) ? (bih0[r] + bhh0[r]) : (bih1[r] + bhh1[r]);
    }
}

// -------------------- group barrier (8 co-resident CTAs) -------------------
__device__ __forceinline__ void group_barrier(int grp) {
    __syncthreads();
    if (threadIdx.x == 0) {
        __threadfence();   // release: make this CTA's h writes visible
        volatile unsigned* genp = &g_bar_gen[grp];
        unsigned gen = *genp;
        unsigned old = atomicAdd(&g_bar_count[grp], 1u);
        if (old == GSIZE - 1) {
            ((volatile unsigned*)&g_bar_count[grp])[0] = 0u;
            __threadfence();
            atomicExch(&g_bar_gen[grp], gen + 1u);
        } else {
            while (*genp == gen) { __nanosleep(64); }
        }
        __threadfence();   // acquire
    }
    __syncthreads();
}

// -------------------- fp32x2 register-tiled GEMM fragment ------------------
// CTA computes G[64 batch, 128 gatecols], K-tile = 32.
// Thread (ty in [0,8), tx in [0,32)): 8 batch rows (as 4 f32x2 pairs) x 4 gates.
struct Frag {
    float4 a0, a1;                 // A: (b, kq*4..) and (b, 16+kq*4..)
    float4 w00, w01, w10, w11;     // W rows kk, kk+16; col halves 0 / +64
};

__device__ __forceinline__ void load_frag(const float* __restrict__ Ag, int lda,
                                          const float* __restrict__ Wrow, int kc,
                                          int tid, bool a_cg, Frag& f) {
    int b = tid >> 2, q = tid & 3;
    const float4* ap0 = (const float4*)(Ag + (size_t)b * lda + kc + q * 4);
    const float4* ap1 = (const float4*)(Ag + (size_t)b * lda + kc + 16 + q * 4);
    f.a0 = a_cg ? __ldcg(ap0) : *ap0;
    f.a1 = a_cg ? __ldcg(ap1) : *ap1;
    int kk = tid >> 4, c = tid & 15;
    const float* wp0 = Wrow + (size_t)(kc + kk) * NG;
    const float* wp1 = Wrow + (size_t)(kc + kk + 16) * NG;
    f.w00 = *(const float4*)(wp0 + 4 * c);
    f.w01 = *(const float4*)(wp0 + 4 * c + 64);
    f.w10 = *(const float4*)(wp1 + 4 * c);
    f.w11 = *(const float4*)(wp1 + 4 * c + 64);
}

__device__ __forceinline__ void store_frag(float (&A_s)[32][68], float (&W_s)[32][128],
                                           int tid, const Frag& f) {
    int b = tid >> 2, q = tid & 3;
    A_s[q * 4 + 0][b] = f.a0.x; A_s[q * 4 + 1][b] = f.a0.y;
    A_s[q * 4 + 2][b] = f.a0.z; A_s[q * 4 + 3][b] = f.a0.w;
    A_s[16 + q * 4 + 0][b] = f.a1.x; A_s[16 + q * 4 + 1][b] = f.a1.y;
    A_s[16 + q * 4 + 2][b] = f.a1.z; A_s[16 + q * 4 + 3][b] = f.a1.w;
    int kk = tid >> 4, c = tid & 15;
    *(float4*)&W_s[kk][4 * c]           = f.w00;
    *(float4*)&W_s[kk][4 * c + 64]      = f.w01;
    *(float4*)&W_s[kk + 16][4 * c]      = f.w10;
    *(float4*)&W_s[kk + 16][4 * c + 64] = f.w11;
}

template <int KT>   // KT in units of 32-k tiles
__device__ __forceinline__ void gemm_acc(unsigned long long (&acc2)[4][4],
                                         const float* __restrict__ Ag, int lda,
                                         const float* __restrict__ Wrow,
                                         float (&A_s)[32][68], float (&W_s)[32][128],
                                         int tid, int tx, int ty, bool a_cg) {
    Frag f;
    load_frag(Ag, lda, Wrow, 0, tid, a_cg, f);
#pragma unroll 1
    for (int kt = 0; kt < KT; ++kt) {
        __syncthreads();
        store_frag(A_s, W_s, tid, f);
        __syncthreads();
        if (kt + 1 < KT) load_frag(Ag, lda, Wrow, (kt + 1) * 32, tid, a_cg, f);
#pragma unroll
        for (int kk = 0; kk < 32; ++kk) {
            const ulonglong2* ap = (const ulonglong2*)&A_s[kk][ty * 8];
            ulonglong2 aA = ap[0];   // pairs (e0,e1), (e2,e3)
            ulonglong2 aB = ap[1];   // pairs (e4,e5), (e6,e7)
            unsigned long long w0 = dup2(W_s[kk][tx]);
            unsigned long long w1 = dup2(W_s[kk][32 + tx]);
            unsigned long long w2 = dup2(W_s[kk][64 + tx]);
            unsigned long long w3 = dup2(W_s[kk][96 + tx]);
            ffma2(acc2[0][0], aA.x, w0); ffma2(acc2[0][1], aA.x, w1);
            ffma2(acc2[0][2], aA.x, w2); ffma2(acc2[0][3], aA.x, w3);
            ffma2(acc2[1][0], aA.y, w0); ffma2(acc2[1][1], aA.y, w1);
            ffma2(acc2[1][2], aA.y, w2); ffma2(acc2[1][3], aA.y, w3);
            ffma2(acc2[2][0], aB.x, w0); ffma2(acc2[2][1], aB.x, w1);
            ffma2(acc2[2][2], aB.x, w2); ffma2(acc2[2][3], aB.x, w3);
            ffma2(acc2[3][0], aB.y, w0); ffma2(acc2[3][1], aB.y, w1);
            ffma2(acc2[3][2], aB.y, w2); ffma2(acc2[3][3], aB.y, w3);
        }
    }
}

__device__ __forceinline__ float sigm(float x) { return 1.f / (1.f + expf(-x)); }

// -------------------- kernel 3: persistent fused 2-layer LSTM --------------
__global__ void __launch_bounds__(256, 1) lstm_kernel(
    const float* __restrict__ h0in, const float* __restrict__ c0in,
    const float* __restrict__ fcw, const float* __restrict__ fcb,
    const float* __restrict__ decw, const float* __restrict__ decb,
    float* __restrict__ out) {
    __shared__ __align__(16) float A_s[32][68];
    __shared__ __align__(16) float W_s[32][128];

    const int tid = threadIdx.x;
    const int tx = tid & 31, ty = tid >> 5;
    const int bi = blockIdx.x >> 3;   // batch group 0..15
    const int hi = blockIdx.x & 7;    // hidden slice 0..7
    const int jg = hi * 32 + tx;      // global hidden index owned by this thread
    const int b0 = bi * 64 + ty * 8;  // first batch row of this thread

    unsigned long long bias0d[4], bias1d[4];
#pragma unroll
    for (int g = 0; g < 4; ++g) {
        bias0d[g] = dup2(g_bias[hi * 128 + g * 32 + tx]);
        bias1d[g] = dup2(g_bias[NG + hi * 128 + g * 32 + tx]);
    }

    float c0r[8], c1r[8];
#pragma unroll
    for (int e = 0; e < 8; ++e) {
        int b = b0 + e;
        c0r[e] = c0in[b * NH + jg];
        c1r[e] = c0in[Bsz * NH + b * NH + jg];
        g_H0[b * NH + jg] = h0in[b * NH + jg];
        g_H1[b * NH + jg] = h0in[Bsz * NH + b * NH + jg];
    }
    group_barrier(bi);

    const float* W0x = g_WT + hi * 128;
    const float* W0h = g_WT + (size_t)KX * NG + hi * 128;
    const float* W1x = g_WT + (size_t)(KX + NH) * NG + hi * 128;
    const float* W1h = g_WT + (size_t)(KX + 2 * NH) * NG + hi * 128;

    int p = 0;
    for (int t = 0; t < Tst; ++t) {
        // ---------------- layer 0 ----------------
        unsigned long long acc2[4][4];
#pragma unroll
        for (int pr = 0; pr < 4; ++pr)
#pragma unroll
            for (int g = 0; g < 4; ++g) acc2[pr][g] = bias0d[g];

        gemm_acc<1>(acc2, g_X + ((size_t)t * Bsz + bi * 64) * KX, KX, W0x,
                    A_s, W_s, tid, tx, ty, false);
        gemm_acc<8>(acc2, g_H0 + (size_t)p * Bsz * NH + bi * 64 * NH, NH, W0h,
                    A_s, W_s, tid, tx, ty, true);
#pragma unroll
        for (int pr = 0; pr < 4; ++pr) {
            float2 vi = unpack2(acc2[pr][0]);
            float2 vf = unpack2(acc2[pr][1]);
            float2 vg = unpack2(acc2[pr][2]);
            float2 vo = unpack2(acc2[pr][3]);
            float gi[2] = {vi.x, vi.y}, gf[2] = {vf.x, vf.y};
            float gg[2] = {vg.x, vg.y}, go[2] = {vo.x, vo.y};
#pragma unroll
            for (int h = 0; h < 2; ++h) {
                int e = 2 * pr + h;
                float c = fmaf(sigm(gf[h]), c0r[e], sigm(gi[h]) * tanhf(gg[h]));
                c0r[e] = c;
                g_H0[(size_t)(1 - p) * Bsz * NH + (b0 + e) * NH + jg] =
                    sigm(go[h]) * tanhf(c);
            }
        }
        group_barrier(bi);

        // ---------------- layer 1 ----------------
#pragma unroll
        for (int pr = 0; pr < 4; ++pr)
#pragma unroll
            for (int g = 0; g < 4; ++g) acc2[pr][g] = bias1d[g];

        gemm_acc<8>(acc2, g_H0 + (size_t)(1 - p) * Bsz * NH + bi * 64 * NH, NH, W1x,
                    A_s, W_s, tid, tx, ty, true);
        gemm_acc<8>(acc2, g_H1 + (size_t)p * Bsz * NH + bi * 64 * NH, NH, W1h,
                    A_s, W_s, tid, tx, ty, true);
#pragma unroll
        for (int pr = 0; pr < 4; ++pr) {
            float2 vi = unpack2(acc2[pr][0]);
            float2 vf = unpack2(acc2[pr][1]);
            float2 vg = unpack2(acc2[pr][2]);
            float2 vo = unpack2(acc2[pr][3]);
            float gi[2] = {vi.x, vi.y}, gf[2] = {vf.x, vf.y};
            float gg[2] = {vg.x, vg.y}, go[2] = {vo.x, vo.y};
#pragma unroll
            for (int h = 0; h < 2; ++h) {
                int e = 2 * pr + h;
                float c = fmaf(sigm(gf[h]), c1r[e], sigm(gi[h]) * tanhf(gg[h]));
                c1r[e] = c;
                g_H1[(size_t)(1 - p) * Bsz * NH + (b0 + e) * NH + jg] =
                    sigm(go[h]) * tanhf(c);
            }
        }
        group_barrier(bi);
        p ^= 1;
    }

    // ---------------- outputs ----------------
    float* outh = out + 2 * Bsz;
    float* outc = outh + 2 * Bsz * NH;
#pragma unroll
    for (int e = 0; e < 8; ++e) {
        int b = b0 + e;
        outh[b * NH + jg]            = g_H0[(size_t)p * Bsz * NH + b * NH + jg];
        outh[Bsz * NH + b * NH + jg] = g_H1[(size_t)p * Bsz * NH + b * NH + jg];
        outc[b * NH + jg]            = c0r[e];
        outc[Bsz * NH + b * NH + jg] = c1r[e];
    }

    // decoded head: only last timestep's layer1 h matters
    if (hi == 0 && tid < 64) {
        int b = bi * 64 + tid;
        const float* h1 = g_H1 + (size_t)p * Bsz * NH + b * NH;
        float d0 = decb[0], d1 = decb[1];
#pragma unroll 1
        for (int m = 0; m < 10; ++m) {
            float s = fcb[m];
            for (int j = 0; j < 256; ++j) s = fmaf(__ldcg(h1 + j), fcw[m * 256 + j], s);
            s = fmaxf(s, 0.f);
            d0 = fmaf(s, decw[m], d0);
            d1 = fmaf(s, decw[10 + m], d1);
        }
        out[b] = d0;
        out[Bsz + b] = d1;
    }
}

// -------------------- launch --------------------
extern "C" void kernel_launch(void* const* d_in, const int* in_sizes, int n_in,
                              void* d_out, int out_size) {
    const int*   input = (const int*)  d_in[0];
    const float* h0    = (const float*)d_in[1];
    const float* c0    = (const float*)d_in[2];
    const float* emb   = (const float*)d_in[3];
    const float* fcw   = (const float*)d_in[4];
    const float* fcb   = (const float*)d_in[5];
    const float* decw  = (const float*)d_in[6];
    const float* decb  = (const float*)d_in[7];
    const float* Wih0  = (const float*)d_in[8];
    const float* Whh0  = (const float*)d_in[9];
    const float* bih0  = (const float*)d_in[10];
    const float* bhh0  = (const float*)d_in[11];
    const float* Wih1  = (const float*)d_in[12];
    const float* Whh1  = (const float*)d_in[13];
    const float* bih1  = (const float*)d_in[14];
    const float* bhh1  = (const float*)d_in[15];
    float* out = (float*)d_out;

    long nX = (long)Tst * Bsz * KX;
    gather_emb_kernel<<<(unsigned)((nX + 255) / 256), 256>>>(input, emb);

    int nW = (KX + 3 * NH) * NG + 2 * NG;
    prep_weights_kernel<<<(nW + 255) / 256, 256>>>(Wih0, Whh0, bih0, bhh0,
                                                   Wih1, Whh1, bih1, bhh1);

    lstm_kernel<<<NCTA, 256>>>(h0, c0, fcw, fcb, decw, decb, out);
}

// round 9
// speedup vs baseline: 1.8097x; 1.8097x over previous
#include <cuda_runtime.h>
#include <cuda_bf16.h>

#define Bsz 1024
#define Tst 300
#define NH  256
#define NBG 8      // batch groups (128 rows)
#define NGS 16     // gate-slice CTAs per group (64 gate cols each)
#define NCTA 128

// W SMEM block indices (2KB blocks of mma-B fragments, one per k16-chunk per hi/lo)
#define BLK_W0XH 0
#define BLK_W0XL 2
#define BLK_W0HH 4
#define BLK_W0HL 20
#define BLK_W1XH 36
#define BLK_W1XL 52
#define BLK_W1HH 68
#define BLK_W1HL 84
#define NBLK     100
#define SMEM_SZ  (NBLK * 2048 + 512)

// -------------------- device scratch --------------------
__device__ unsigned g_Wfrag[(size_t)NGS * NBLK * 512];        // 3.3 MB
__device__ float    g_biasP[2 * NGS * 64];
__device__ unsigned g_Xfrag[(size_t)Tst * NBG * 8 * 2 * 256]; // 78.6 MB
__device__ unsigned g_Hfrag[2 * 2 * NBG * 8 * 16 * 256];      // 4 MB [l][buf][bg][mt][ch][hl][lane][reg]
__device__ unsigned g_bar_count[NBG];
__device__ unsigned g_bar_gen[NBG];

__device__ __forceinline__ size_t hoff(int l, int buf, int bg, int mt, int ch) {
    return ((((((size_t)(l * 2 + buf)) * NBG + bg) * 8 + mt) * 16 + ch) * 256);
}
__device__ __forceinline__ size_t xoff(int t, int bg, int mt, int c) {
    return ((((size_t)t * NBG + bg) * 8 + mt) * 2 + c) * 256;
}

__device__ __forceinline__ void split2(float v0, float v1, unsigned& hi, unsigned& lo) {
    __nv_bfloat16 h0 = __float2bfloat16(v0), h1 = __float2bfloat16(v1);
    __nv_bfloat16 l0 = __float2bfloat16(v0 - __bfloat162float(h0));
    __nv_bfloat16 l1 = __float2bfloat16(v1 - __bfloat162float(h1));
    hi = (unsigned)__bfloat16_as_ushort(h0) | ((unsigned)__bfloat16_as_ushort(h1) << 16);
    lo = (unsigned)__bfloat16_as_ushort(l0) | ((unsigned)__bfloat16_as_ushort(l1) << 16);
}
__device__ __forceinline__ float sigm(float x) { return 1.f / (1.f + __expf(-x)); }
__device__ __forceinline__ float tanh_f(float x) {
    x = fminf(fmaxf(x, -15.f), 15.f);
    float e = __expf(2.f * x);
    return __fdividef(e - 1.f, e + 1.f);
}

__device__ __forceinline__ void mma4(float* d, const unsigned* a, unsigned b0, unsigned b1) {
    asm volatile("mma.sync.aligned.m16n8k16.row.col.f32.bf16.bf16.f32 "
        "{%0,%1,%2,%3}, {%4,%5,%6,%7}, {%8,%9}, {%0,%1,%2,%3};"
        : "+f"(d[0]), "+f"(d[1]), "+f"(d[2]), "+f"(d[3])
        : "r"(a[0]), "r"(a[1]), "r"(a[2]), "r"(a[3]), "r"(b0), "r"(b1));
}

// -------------------- x gather (from round-3 verified mapping) --------------
__device__ __forceinline__ float fetch_x(const int* __restrict__ input,
                                         const float* __restrict__ emb,
                                         int t, int b, int k) {
    if (k >= 25) return 0.f;
    long flat = (long)t * (Bsz * 25) + b * 25 + k;
    int s = (int)(flat / (Bsz * 300));
    int rr = (int)(flat % (Bsz * 300));
    int bb = rr / 300, e = rr % 300;
    return emb[(long)input[bb * 25 + s] * 300 + e];
}

// -------------------- prep kernels --------------------
__global__ void pack_x_kernel(const int* __restrict__ input, const float* __restrict__ emb) {
    unsigned idx = blockIdx.x * blockDim.x + threadIdx.x;
    if (idx >= (unsigned)Tst * NBG * 8 * 2 * 32) return;
    int lane = idx & 31;
    unsigned r = idx >> 5;
    int c = r & 1; r >>= 1;
    int mt = r & 7; r >>= 3;
    int bg = r & 7;
    int t = r >> 3;
    unsigned ohi[4], olo[4];
#pragma unroll
    for (int reg = 0; reg < 4; ++reg) {
        int row = mt * 16 + (lane >> 2) + (reg & 1) * 8;
        int b = bg * 128 + row;
        int k = c * 16 + ((reg >> 1) & 1) * 8 + 2 * (lane & 3);
        float v0 = fetch_x(input, emb, t, b, k);
        float v1 = fetch_x(input, emb, t, b, k + 1);
        split2(v0, v1, ohi[reg], olo[reg]);
    }
    unsigned* base = g_Xfrag + (size_t)(idx >> 5) * 256;
    *(uint4*)(base + lane * 4)       = make_uint4(ohi[0], ohi[1], ohi[2], ohi[3]);
    *(uint4*)(base + 128 + lane * 4) = make_uint4(olo[0], olo[1], olo[2], olo[3]);
}

__global__ void prep_w_kernel(
    const float* __restrict__ Wih0, const float* __restrict__ Whh0,
    const float* __restrict__ bih0, const float* __restrict__ bhh0,
    const float* __restrict__ Wih1, const float* __restrict__ Whh1,
    const float* __restrict__ bih1, const float* __restrict__ bhh1) {
    const int NWF = NGS * NBLK * 512;
    int idx = blockIdx.x * blockDim.x + threadIdx.x;
    if (idx < NWF) {
        int hs = idx / (NBLK * 512);
        int rem = idx % (NBLK * 512);
        int blk = rem / 512, q = rem % 512;
        int L = (q >> 2) & 31, w = q & 3, i = q >> 7;
        int j = i * 4 + w;
        int nt = j >> 1, regb = j & 1;
        int mat, ch, hl;
        if (blk < 4) { mat = 0; hl = blk >> 1; ch = blk & 1; }
        else { int bb = blk - 4; mat = 1 + bb / 32; int cc = bb % 32; hl = cc >> 4; ch = cc & 15; }
        int k = ch * 16 + regb * 8 + 2 * (L & 3);
        int nl = nt * 8 + (L >> 2);
        int r = (nl >> 4) * 256 + hs * 16 + (nl & 15);
        float v0 = 0.f, v1 = 0.f;
        if (mat == 0) {
            if (k < 25)     v0 = Wih0[r * 25 + k];
            if (k + 1 < 25) v1 = Wih0[r * 25 + k + 1];
        } else if (mat == 1) { v0 = Whh0[r * 256 + k]; v1 = Whh0[r * 256 + k + 1]; }
        else if (mat == 2)   { v0 = Wih1[r * 256 + k]; v1 = Wih1[r * 256 + k + 1]; }
        else                 { v0 = Whh1[r * 256 + k]; v1 = Whh1[r * 256 + k + 1]; }
        unsigned hi, lo;
        split2(v0, v1, hi, lo);
        g_Wfrag[idx] = hl ? lo : hi;
    } else if (idx < NWF + 2048) {
        int i2 = idx - NWF;
        int l = i2 >> 10, rest = i2 & 1023, hs = rest >> 6, nl = rest & 63;
        int r = (nl >> 4) * 256 + hs * 16 + (nl & 15);
        g_biasP[i2] = (l == 0) ? (bih0[r] + bhh0[r]) : (bih1[r] + bhh1[r]);
    }
}

__global__ void init_h_kernel(const float* __restrict__ h0in) {
    unsigned idx = blockIdx.x * blockDim.x + threadIdx.x;
    if (idx >= 2u * NBG * 8 * 16 * 32) return;
    int lane = idx & 31;
    unsigned r = idx >> 5;
    int ch = r & 15; r >>= 4;
    int mt = r & 7; r >>= 3;
    int bg = r & 7;
    int l = r >> 3;
    unsigned ohi[4], olo[4];
#pragma unroll
    for (int reg = 0; reg < 4; ++reg) {
        int row = mt * 16 + (lane >> 2) + (reg & 1) * 8;
        int b = bg * 128 + row;
        int j = ch * 16 + ((reg >> 1) & 1) * 8 + 2 * (lane & 3);
        const float* src = h0in + (size_t)l * (Bsz * NH) + b * 256 + j;
        split2(src[0], src[1], ohi[reg], olo[reg]);
    }
    unsigned* base = g_Hfrag + hoff(l, 0, bg, mt, ch);
    *(uint4*)(base + lane * 4)       = make_uint4(ohi[0], ohi[1], ohi[2], ohi[3]);
    *(uint4*)(base + 128 + lane * 4) = make_uint4(olo[0], olo[1], olo[2], olo[3]);
}

// -------------------- group barrier (16 co-resident CTAs) ------------------
__device__ __forceinline__ void group_barrier(int grp) {
    __syncthreads();
    if (threadIdx.x == 0) {
        __threadfence();
        volatile unsigned* genp = &g_bar_gen[grp];
        unsigned gen = *genp;
        unsigned old = atomicAdd(&g_bar_count[grp], 1u);
        if (old == NGS - 1) {
            ((volatile unsigned*)&g_bar_count[grp])[0] = 0u;
            __threadfence();
            atomicExch(&g_bar_gen[grp], gen + 1u);
        } else {
            while (*genp == gen) { __nanosleep(64); }
        }
        __threadfence();
    }
    __syncthreads();
}

// -------------------- one k16 chunk: 3 split passes -------------------------
__device__ __forceinline__ void do_chunk(float (&acc)[8][4],
        const unsigned* __restrict__ A, const uint4* __restrict__ smq,
        int blkh, int blkl, int lane) {
    uint4 ahv = __ldcg((const uint4*)(A + lane * 4));
    uint4 alv = __ldcg((const uint4*)(A + 128 + lane * 4));
    unsigned ah[4] = {ahv.x, ahv.y, ahv.z, ahv.w};
    unsigned al[4] = {alv.x, alv.y, alv.z, alv.w};
    const uint4* WH = smq + blkh * 128;
    uint4 q0 = WH[lane], q1 = WH[32 + lane], q2 = WH[64 + lane], q3 = WH[96 + lane];
    unsigned wb[16] = {q0.x,q0.y,q0.z,q0.w, q1.x,q1.y,q1.z,q1.w,
                       q2.x,q2.y,q2.z,q2.w, q3.x,q3.y,q3.z,q3.w};
#pragma unroll
    for (int nt = 0; nt < 8; ++nt) mma4(acc[nt], ah, wb[2*nt], wb[2*nt+1]);
#pragma unroll
    for (int nt = 0; nt < 8; ++nt) mma4(acc[nt], al, wb[2*nt], wb[2*nt+1]);
    const uint4* WL = smq + blkl * 128;
    q0 = WL[lane]; q1 = WL[32 + lane]; q2 = WL[64 + lane]; q3 = WL[96 + lane];
    unsigned wc[16] = {q0.x,q0.y,q0.z,q0.w, q1.x,q1.y,q1.z,q1.w,
                       q2.x,q2.y,q2.z,q2.w, q3.x,q3.y,q3.z,q3.w};
#pragma unroll
    for (int nt = 0; nt < 8; ++nt) mma4(acc[nt], ah, wc[2*nt], wc[2*nt+1]);
}

// -------------------- epilogue: gates -> c,h; write h fragments -------------
__device__ __forceinline__ void epilogue(int l, int pnew, int bg, int mt, int hs, int lane,
        float (&acc)[8][4], float (&cs)[2][4], const float* __restrict__ bias_s,
        float* __restrict__ outH) {
    int a = lane & 3;
    unsigned* base = g_Hfrag + hoff(l, pnew, bg, mt, hs);
    int lanep = (lane >> 2) * 4 + a;
#pragma unroll
    for (int rs = 0; rs < 2; ++rs) {
        float hv[4];
#pragma unroll
        for (int ui = 0; ui < 4; ++ui) {
            int u = ((ui >> 1) << 3) + 2 * a + (ui & 1);
            int sub = ui >> 1, dr = rs * 2 + (ui & 1);
            float gi = acc[sub][dr]     + bias_s[l * 64 + u];
            float gf = acc[2 + sub][dr] + bias_s[l * 64 + 16 + u];
            float gg = acc[4 + sub][dr] + bias_s[l * 64 + 32 + u];
            float go = acc[6 + sub][dr] + bias_s[l * 64 + 48 + u];
            float c = fmaf(sigm(gf), cs[rs][ui], sigm(gi) * tanh_f(gg));
            cs[rs][ui] = c;
            hv[ui] = sigm(go) * tanh_f(c);
        }
#pragma unroll
        for (int pp = 0; pp < 2; ++pp) {
            unsigned hi, lo;
            split2(hv[2 * pp], hv[2 * pp + 1], hi, lo);
            int reg = rs + 2 * pp;
            base[lanep * 4 + reg]       = hi;
            base[128 + lanep * 4 + reg] = lo;
        }
        if (outH) {
            int b_row = bg * 128 + mt * 16 + (lane >> 2) + rs * 8;
#pragma unroll
            for (int ui = 0; ui < 4; ++ui) {
                int u = ((ui >> 1) << 3) + 2 * a + (ui & 1);
                outH[(size_t)l * Bsz * NH + b_row * 256 + hs * 16 + u] = hv[ui];
            }
        }
    }
}

// -------------------- main persistent kernel --------------------
__global__ void __launch_bounds__(256, 1) lstm_kernel(
    const float* __restrict__ h0in, const float* __restrict__ c0in,
    float* __restrict__ out) {
    extern __shared__ uint4 smq[];
    const int tid = threadIdx.x, lane = tid & 31, mt = tid >> 5;
    const int bg = blockIdx.x >> 4, hs = blockIdx.x & 15;
    const int a = lane & 3;

    const uint4* wsrc = (const uint4*)g_Wfrag + (size_t)hs * (NBLK * 128);
    for (int i = tid; i < NBLK * 128; i += 256) smq[i] = wsrc[i];
    float* bias_s = (float*)(smq + NBLK * 128);
    if (tid < 128) bias_s[tid] = g_biasP[(tid >> 6) * 1024 + hs * 64 + (tid & 63)];
    __syncthreads();

    float cs0[2][4], cs1[2][4];
#pragma unroll
    for (int rs = 0; rs < 2; ++rs)
#pragma unroll
        for (int ui = 0; ui < 4; ++ui) {
            int u = ((ui >> 1) << 3) + 2 * a + (ui & 1);
            int b_row = bg * 128 + mt * 16 + (lane >> 2) + rs * 8;
            int j = hs * 16 + u;
            cs0[rs][ui] = c0in[b_row * 256 + j];
            cs1[rs][ui] = c0in[Bsz * NH + b_row * 256 + j];
        }

    float* outH = out + 2 * Bsz;
    int p = 0;
#pragma unroll 1
    for (int t = 0; t < Tst; ++t) {
        float acc[8][4];
#pragma unroll
        for (int nt = 0; nt < 8; ++nt)
#pragma unroll
            for (int d = 0; d < 4; ++d) acc[nt][d] = 0.f;

#pragma unroll 1
        for (int c = 0; c < 2; ++c)
            do_chunk(acc, g_Xfrag + xoff(t, bg, mt, c), smq, BLK_W0XH + c, BLK_W0XL + c, lane);
#pragma unroll 1
        for (int c = 0; c < 16; ++c)
            do_chunk(acc, g_Hfrag + hoff(0, p, bg, mt, c), smq, BLK_W0HH + c, BLK_W0HL + c, lane);

        epilogue(0, 1 - p, bg, mt, hs, lane, acc, cs0, bias_s, (t == Tst - 1) ? outH : nullptr);
        group_barrier(bg);

#pragma unroll
        for (int nt = 0; nt < 8; ++nt)
#pragma unroll
            for (int d = 0; d < 4; ++d) acc[nt][d] = 0.f;

#pragma unroll 1
        for (int c = 0; c < 16; ++c)
            do_chunk(acc, g_Hfrag + hoff(0, 1 - p, bg, mt, c), smq, BLK_W1XH + c, BLK_W1XL + c, lane);
#pragma unroll 1
        for (int c = 0; c < 16; ++c)
            do_chunk(acc, g_Hfrag + hoff(1, p, bg, mt, c), smq, BLK_W1HH + c, BLK_W1HL + c, lane);

        epilogue(1, 1 - p, bg, mt, hs, lane, acc, cs1, bias_s, (t == Tst - 1) ? outH : nullptr);
        group_barrier(bg);
        p ^= 1;
    }

    float* outC = out + 2 * Bsz + 2 * Bsz * NH;
#pragma unroll
    for (int rs = 0; rs < 2; ++rs)
#pragma unroll
        for (int ui = 0; ui < 4; ++ui) {
            int u = ((ui >> 1) << 3) + 2 * a + (ui & 1);
            int b_row = bg * 128 + mt * 16 + (lane >> 2) + rs * 8;
            int j = hs * 16 + u;
            outC[b_row * 256 + j] = cs0[rs][ui];
            outC[Bsz * NH + b_row * 256 + j] = cs1[rs][ui];
        }
}

// -------------------- decoded head --------------------
__global__ void decode_kernel(const float* __restrict__ fcw, const float* __restrict__ fcb,
                              const float* __restrict__ decw, const float* __restrict__ decb,
                              float* __restrict__ out) {
    int b = blockIdx.x * blockDim.x + threadIdx.x;
    if (b >= Bsz) return;
    const float* h1 = out + 2 * Bsz + Bsz * NH + b * 256;
    float d0 = decb[0], d1 = decb[1];
#pragma unroll 1
    for (int m = 0; m < 10; ++m) {
        float s = fcb[m];
        for (int j = 0; j < 256; ++j) s = fmaf(h1[j], fcw[m * 256 + j], s);
        s = fmaxf(s, 0.f);
        d0 = fmaf(s, decw[m], d0);
        d1 = fmaf(s, decw[10 + m], d1);
    }
    out[b] = d0;
    out[Bsz + b] = d1;
}

// -------------------- launch --------------------
extern "C" void kernel_launch(void* const* d_in, const int* in_sizes, int n_in,
                              void* d_out, int out_size) {
    const int*   input = (const int*)  d_in[0];
    const float* h0    = (const float*)d_in[1];
    const float* c0    = (const float*)d_in[2];
    const float* emb   = (const float*)d_in[3];
    const float* fcw   = (const float*)d_in[4];
    const float* fcb   = (const float*)d_in[5];
    const float* decw  = (const float*)d_in[6];
    const float* decb  = (const float*)d_in[7];
    float* out = (float*)d_out;

    cudaFuncSetAttribute(lstm_kernel, cudaFuncAttributeMaxDynamicSharedMemorySize, SMEM_SZ);

    unsigned nX = Tst * NBG * 8 * 2 * 32;
    pack_x_kernel<<<(nX + 255) / 256, 256>>>(input, emb);
    int nW = NGS * NBLK * 512 + 2048;
    prep_w_kernel<<<(nW + 255) / 256, 256>>>(
        (const float*)d_in[8], (const float*)d_in[9], (const float*)d_in[10], (const float*)d_in[11],
        (const float*)d_in[12], (const float*)d_in[13], (const float*)d_in[14], (const float*)d_in[15]);
    unsigned nH = 2 * NBG * 8 * 16 * 32;
    init_h_kernel<<<(nH + 255) / 256, 256>>>(h0);
    lstm_kernel<<<NCTA, 256, SMEM_SZ>>>(h0, c0, out);
    decode_kernel<<<(Bsz + 255) / 256, 256>>>(fcw, fcb, decw, decb, out);
}

// round 10
// speedup vs baseline: 2.1256x; 1.1746x over previous
#include <cuda_runtime.h>
#include <cuda_bf16.h>

#define Bsz 1024
#define Tst 300
#define NH  256
#define NBG 8      // batch groups (128 rows)
#define NGS 16     // gate-slice CTAs per group (64 gate cols each)
#define NCTA 128

// W SMEM block indices (2KB blocks of mma-B fragments, one per k16-chunk per hi/lo)
#define BLK_W0XH 0
#define BLK_W0XL 2
#define BLK_W0HH 4
#define BLK_W0HL 20
#define BLK_W1XH 36
#define BLK_W1XL 52
#define BLK_W1HH 68
#define BLK_W1HL 84
#define NBLK     100
#define SMEM_SZ  (NBLK * 2048 + 512)

// -------------------- device scratch --------------------
__device__ unsigned g_Wfrag[(size_t)NGS * NBLK * 512];        // 3.3 MB
__device__ float    g_biasP[2 * NGS * 64];
__device__ unsigned g_Xfrag[(size_t)Tst * NBG * 8 * 2 * 256]; // 78.6 MB
__device__ unsigned g_Hfrag[2 * 2 * NBG * 8 * 16 * 256];      // 4 MB
__device__ unsigned g_cntA[NBG], g_genA[NBG];
__device__ unsigned g_cntB[NBG], g_genB[NBG];

__device__ __forceinline__ size_t hoff(int l, int buf, int bg, int mt, int ch) {
    return ((((((size_t)(l * 2 + buf)) * NBG + bg) * 8 + mt) * 16 + ch) * 256);
}
__device__ __forceinline__ size_t xoff(int t, int bg, int mt, int c) {
    return ((((size_t)t * NBG + bg) * 8 + mt) * 2 + c) * 256;
}

__device__ __forceinline__ void split2(float v0, float v1, unsigned& hi, unsigned& lo) {
    __nv_bfloat16 h0 = __float2bfloat16(v0), h1 = __float2bfloat16(v1);
    __nv_bfloat16 l0 = __float2bfloat16(v0 - __bfloat162float(h0));
    __nv_bfloat16 l1 = __float2bfloat16(v1 - __bfloat162float(h1));
    hi = (unsigned)__bfloat16_as_ushort(h0) | ((unsigned)__bfloat16_as_ushort(h1) << 16);
    lo = (unsigned)__bfloat16_as_ushort(l0) | ((unsigned)__bfloat16_as_ushort(l1) << 16);
}
__device__ __forceinline__ float sigm(float x) { return 1.f / (1.f + __expf(-x)); }
__device__ __forceinline__ float tanh_f(float x) {
    x = fminf(fmaxf(x, -15.f), 15.f);
    float e = __expf(2.f * x);
    return __fdividef(e - 1.f, e + 1.f);
}

__device__ __forceinline__ void mma4(float* d, const unsigned* a, unsigned b0, unsigned b1) {
    asm volatile("mma.sync.aligned.m16n8k16.row.col.f32.bf16.bf16.f32 "
        "{%0,%1,%2,%3}, {%4,%5,%6,%7}, {%8,%9}, {%0,%1,%2,%3};"
        : "+f"(d[0]), "+f"(d[1]), "+f"(d[2]), "+f"(d[3])
        : "r"(a[0]), "r"(a[1]), "r"(a[2]), "r"(a[3]), "r"(b0), "r"(b1));
}

// -------------------- x gather --------------------
__device__ __forceinline__ float fetch_x(const int* __restrict__ input,
                                         const float* __restrict__ emb,
                                         int t, int b, int k) {
    if (k >= 25) return 0.f;
    long flat = (long)t * (Bsz * 25) + b * 25 + k;
    int s = (int)(flat / (Bsz * 300));
    int rr = (int)(flat % (Bsz * 300));
    int bb = rr / 300, e = rr % 300;
    return emb[(long)input[bb * 25 + s] * 300 + e];
}

// -------------------- prep kernels --------------------
__global__ void pack_x_kernel(const int* __restrict__ input, const float* __restrict__ emb) {
    unsigned idx = blockIdx.x * blockDim.x + threadIdx.x;
    if (idx >= (unsigned)Tst * NBG * 8 * 2 * 32) return;
    int lane = idx & 31;
    unsigned r = idx >> 5;
    int c = r & 1; r >>= 1;
    int mt = r & 7; r >>= 3;
    int bg = r & 7;
    int t = r >> 3;
    unsigned ohi[4], olo[4];
#pragma unroll
    for (int reg = 0; reg < 4; ++reg) {
        int row = mt * 16 + (lane >> 2) + (reg & 1) * 8;
        int b = bg * 128 + row;
        int k = c * 16 + ((reg >> 1) & 1) * 8 + 2 * (lane & 3);
        float v0 = fetch_x(input, emb, t, b, k);
        float v1 = fetch_x(input, emb, t, b, k + 1);
        split2(v0, v1, ohi[reg], olo[reg]);
    }
    unsigned* base = g_Xfrag + (size_t)(idx >> 5) * 256;
    *(uint4*)(base + lane * 4)       = make_uint4(ohi[0], ohi[1], ohi[2], ohi[3]);
    *(uint4*)(base + 128 + lane * 4) = make_uint4(olo[0], olo[1], olo[2], olo[3]);
}

__global__ void prep_w_kernel(
    const float* __restrict__ Wih0, const float* __restrict__ Whh0,
    const float* __restrict__ bih0, const float* __restrict__ bhh0,
    const float* __restrict__ Wih1, const float* __restrict__ Whh1,
    const float* __restrict__ bih1, const float* __restrict__ bhh1) {
    const int NWF = NGS * NBLK * 512;
    int idx = blockIdx.x * blockDim.x + threadIdx.x;
    if (idx < NWF) {
        int hs = idx / (NBLK * 512);
        int rem = idx % (NBLK * 512);
        int blk = rem / 512, q = rem % 512;
        int L = (q >> 2) & 31, w = q & 3, i = q >> 7;
        int j = i * 4 + w;
        int nt = j >> 1, regb = j & 1;
        int mat, ch, hl;
        if (blk < 4) { mat = 0; hl = blk >> 1; ch = blk & 1; }
        else { int bb = blk - 4; mat = 1 + bb / 32; int cc = bb % 32; hl = cc >> 4; ch = cc & 15; }
        int k = ch * 16 + regb * 8 + 2 * (L & 3);
        int nl = nt * 8 + (L >> 2);
        int r = (nl >> 4) * 256 + hs * 16 + (nl & 15);
        float v0 = 0.f, v1 = 0.f;
        if (mat == 0) {
            if (k < 25)     v0 = Wih0[r * 25 + k];
            if (k + 1 < 25) v1 = Wih0[r * 25 + k + 1];
        } else if (mat == 1) { v0 = Whh0[r * 256 + k]; v1 = Whh0[r * 256 + k + 1]; }
        else if (mat == 2)   { v0 = Wih1[r * 256 + k]; v1 = Wih1[r * 256 + k + 1]; }
        else                 { v0 = Whh1[r * 256 + k]; v1 = Whh1[r * 256 + k + 1]; }
        unsigned hi, lo;
        split2(v0, v1, hi, lo);
        g_Wfrag[idx] = hl ? lo : hi;
    } else if (idx < NWF + 2048) {
        int i2 = idx - NWF;
        int l = i2 >> 10, rest = i2 & 1023, hs = rest >> 6, nl = rest & 63;
        int r = (nl >> 4) * 256 + hs * 16 + (nl & 15);
        g_biasP[i2] = (l == 0) ? (bih0[r] + bhh0[r]) : (bih1[r] + bhh1[r]);
    }
}

__global__ void init_h_kernel(const float* __restrict__ h0in) {
    unsigned idx = blockIdx.x * blockDim.x + threadIdx.x;
    if (idx < NBG) {   // reset split-barrier state every replay
        g_cntA[idx] = 0; g_genA[idx] = 0;
        g_cntB[idx] = 0; g_genB[idx] = 0;
    }
    if (idx >= 2u * NBG * 8 * 16 * 32) return;
    int lane = idx & 31;
    unsigned r = idx >> 5;
    int ch = r & 15; r >>= 4;
    int mt = r & 7; r >>= 3;
    int bg = r & 7;
    int l = r >> 3;
    unsigned ohi[4], olo[4];
#pragma unroll
    for (int reg = 0; reg < 4; ++reg) {
        int row = mt * 16 + (lane >> 2) + (reg & 1) * 8;
        int b = bg * 128 + row;
        int j = ch * 16 + ((reg >> 1) & 1) * 8 + 2 * (lane & 3);
        const float* src = h0in + (size_t)l * (Bsz * NH) + b * 256 + j;
        split2(src[0], src[1], ohi[reg], olo[reg]);
    }
    unsigned* base = g_Hfrag + hoff(l, 0, bg, mt, ch);
    *(uint4*)(base + lane * 4)       = make_uint4(ohi[0], ohi[1], ohi[2], ohi[3]);
    *(uint4*)(base + 128 + lane * 4) = make_uint4(olo[0], olo[1], olo[2], olo[3]);
}

// -------------------- split group barrier --------------------
__device__ __forceinline__ void bar_arrive(unsigned* cnt, unsigned* gen, int grp) {
    __syncthreads();
    if (threadIdx.x == 0) {
        __threadfence();
        unsigned old = atomicAdd(&cnt[grp], 1u);
        if (old == NGS - 1) {
            atomicExch(&cnt[grp], 0u);
            __threadfence();
            atomicAdd(&gen[grp], 1u);
        }
    }
}
__device__ __forceinline__ void bar_wait(unsigned* gen, int grp, unsigned target) {
    if (threadIdx.x == 0) {
        volatile unsigned* gp = gen + grp;
        while (*gp < target) __nanosleep(32);
        __threadfence();
    }
    __syncthreads();
}

// -------------------- pipelined chunk pieces --------------------
struct AF { unsigned h[4], l[4]; };

__device__ __forceinline__ AF lda(const unsigned* __restrict__ A, int lane) {
    AF f;
    uint4 a = __ldcg((const uint4*)(A + lane * 4));
    uint4 b = __ldcg((const uint4*)(A + 128 + lane * 4));
    f.h[0]=a.x; f.h[1]=a.y; f.h[2]=a.z; f.h[3]=a.w;
    f.l[0]=b.x; f.l[1]=b.y; f.l[2]=b.z; f.l[3]=b.w;
    return f;
}

__device__ __forceinline__ void compute_chunk(float (&acc)[8][4], const AF& f,
        const uint4* __restrict__ smq, int blkh, int blkl, int lane) {
    const uint4* WH = smq + blkh * 128;
    uint4 q0 = WH[lane], q1 = WH[32 + lane], q2 = WH[64 + lane], q3 = WH[96 + lane];
    unsigned wb[16] = {q0.x,q0.y,q0.z,q0.w, q1.x,q1.y,q1.z,q1.w,
                       q2.x,q2.y,q2.z,q2.w, q3.x,q3.y,q3.z,q3.w};
#pragma unroll
    for (int nt = 0; nt < 8; ++nt) mma4(acc[nt], f.h, wb[2*nt], wb[2*nt+1]);
#pragma unroll
    for (int nt = 0; nt < 8; ++nt) mma4(acc[nt], f.l, wb[2*nt], wb[2*nt+1]);
    const uint4* WL = smq + blkl * 128;
    q0 = WL[lane]; q1 = WL[32 + lane]; q2 = WL[64 + lane]; q3 = WL[96 + lane];
    unsigned wc[16] = {q0.x,q0.y,q0.z,q0.w, q1.x,q1.y,q1.z,q1.w,
                       q2.x,q2.y,q2.z,q2.w, q3.x,q3.y,q3.z,q3.w};
#pragma unroll
    for (int nt = 0; nt < 8; ++nt) mma4(acc[nt], f.h, wc[2*nt], wc[2*nt+1]);
}

// -------------------- epilogue --------------------
__device__ __forceinline__ void epilogue(int l, int pnew, int bg, int mt, int hs, int lane,
        float (&acc)[8][4], float (&cs)[2][4], const float* __restrict__ bias_s,
        float* __restrict__ outH) {
    int a = lane & 3;
    unsigned* base = g_Hfrag + hoff(l, pnew, bg, mt, hs);
    int lanep = (lane >> 2) * 4 + a;
#pragma unroll
    for (int rs = 0; rs < 2; ++rs) {
        float hv[4];
#pragma unroll
        for (int ui = 0; ui < 4; ++ui) {
            int u = ((ui >> 1) << 3) + 2 * a + (ui & 1);
            int sub = ui >> 1, dr = rs * 2 + (ui & 1);
            float gi = acc[sub][dr]     + bias_s[l * 64 + u];
            float gf = acc[2 + sub][dr] + bias_s[l * 64 + 16 + u];
            float gg = acc[4 + sub][dr] + bias_s[l * 64 + 32 + u];
            float go = acc[6 + sub][dr] + bias_s[l * 64 + 48 + u];
            float c = fmaf(sigm(gf), cs[rs][ui], sigm(gi) * tanh_f(gg));
            cs[rs][ui] = c;
            hv[ui] = sigm(go) * tanh_f(c);
        }
#pragma unroll
        for (int pp = 0; pp < 2; ++pp) {
            unsigned hi, lo;
            split2(hv[2 * pp], hv[2 * pp + 1], hi, lo);
            int reg = rs + 2 * pp;
            base[lanep * 4 + reg]       = hi;
            base[128 + lanep * 4 + reg] = lo;
        }
        if (outH) {
            int b_row = bg * 128 + mt * 16 + (lane >> 2) + rs * 8;
#pragma unroll
            for (int ui = 0; ui < 4; ++ui) {
                int u = ((ui >> 1) << 3) + 2 * a + (ui & 1);
                outH[(size_t)l * Bsz * NH + b_row * 256 + hs * 16 + u] = hv[ui];
            }
        }
    }
}

// -------------------- main persistent kernel --------------------
__global__ void __launch_bounds__(256, 1) lstm_kernel(
    const float* __restrict__ h0in, const float* __restrict__ c0in,
    float* __restrict__ out) {
    extern __shared__ uint4 smq[];
    const int tid = threadIdx.x, lane = tid & 31, mt = tid >> 5;
    const int bg = blockIdx.x >> 4, hs = blockIdx.x & 15;
    const int a = lane & 3;

    const uint4* wsrc = (const uint4*)g_Wfrag + (size_t)hs * (NBLK * 128);
    for (int i = tid; i < NBLK * 128; i += 256) smq[i] = wsrc[i];
    float* bias_s = (float*)(smq + NBLK * 128);
    if (tid < 128) bias_s[tid] = g_biasP[(tid >> 6) * 1024 + hs * 64 + (tid & 63)];
    __syncthreads();

    float cs0[2][4], cs1[2][4];
#pragma unroll
    for (int rs = 0; rs < 2; ++rs)
#pragma unroll
        for (int ui = 0; ui < 4; ++ui) {
            int u = ((ui >> 1) << 3) + 2 * a + (ui & 1);
            int b_row = bg * 128 + mt * 16 + (lane >> 2) + rs * 8;
            int j = hs * 16 + u;
            cs0[rs][ui] = c0in[b_row * 256 + j];
            cs1[rs][ui] = c0in[Bsz * NH + b_row * 256 + j];
        }

    float* outH = out + 2 * Bsz;
    int p = 0;
#pragma unroll 1
    for (int t = 0; t < Tst; ++t) {
        float acc[8][4];
#pragma unroll
        for (int nt = 0; nt < 8; ++nt)
#pragma unroll
            for (int d = 0; d < 4; ++d) acc[nt][d] = 0.f;

        // ---- L0: x chunks + W0h*h0[p], depth-2 prefetch ----
        {
            AF cur = lda(g_Xfrag + xoff(t, bg, mt, 0), lane);
            AF nxt = lda(g_Xfrag + xoff(t, bg, mt, 1), lane);
            compute_chunk(acc, cur, smq, BLK_W0XH + 0, BLK_W0XL + 0, lane);
            cur = nxt;
            nxt = lda(g_Hfrag + hoff(0, p, bg, mt, 0), lane);
            compute_chunk(acc, cur, smq, BLK_W0XH + 1, BLK_W0XL + 1, lane);
#pragma unroll 1
            for (int c = 0; c < 16; ++c) {
                cur = nxt;
                if (c < 15) nxt = lda(g_Hfrag + hoff(0, p, bg, mt, c + 1), lane);
                compute_chunk(acc, cur, smq, BLK_W0HH + c, BLK_W0HL + c, lane);
            }
        }
        epilogue(0, 1 - p, bg, mt, hs, lane, acc, cs0, bias_s, (t == Tst - 1) ? outH : nullptr);
        bar_arrive(g_cntA, g_genA, bg);

        // ---- overlap barrier B wait with nothing (it's stale by now) ----
        bar_wait(g_genB, bg, (unsigned)t);    // h1[p] (written step t-1) visible

#pragma unroll
        for (int nt = 0; nt < 8; ++nt)
#pragma unroll
            for (int d = 0; d < 4; ++d) acc[nt][d] = 0.f;

        // ---- L1 part A: W1h*h1[p] (independent of this step's h0) ----
        {
            AF cur = lda(g_Hfrag + hoff(1, p, bg, mt, 0), lane);
            AF nxt = cur;
#pragma unroll 1
            for (int c = 0; c < 16; ++c) {
                if (c < 15) nxt = lda(g_Hfrag + hoff(1, p, bg, mt, c + 1), lane);
                compute_chunk(acc, cur, smq, BLK_W1HH + c, BLK_W1HL + c, lane);
                cur = nxt;
            }
        }
        // ---- now require everyone's h0[1-p] ----
        bar_wait(g_genA, bg, (unsigned)(t + 1));

        // ---- L1 part B: W1x*h0[1-p] ----
        {
            AF cur = lda(g_Hfrag + hoff(0, 1 - p, bg, mt, 0), lane);
            AF nxt = cur;
#pragma unroll 1
            for (int c = 0; c < 16; ++c) {
                if (c < 15) nxt = lda(g_Hfrag + hoff(0, 1 - p, bg, mt, c + 1), lane);
                compute_chunk(acc, cur, smq, BLK_W1XH + c, BLK_W1XL + c, lane);
                cur = nxt;
            }
        }
        epilogue(1, 1 - p, bg, mt, hs, lane, acc, cs1, bias_s, (t == Tst - 1) ? outH : nullptr);
        bar_arrive(g_cntB, g_genB, bg);
        p ^= 1;
    }

    float* outC = out + 2 * Bsz + 2 * Bsz * NH;
#pragma unroll
    for (int rs = 0; rs < 2; ++rs)
#pragma unroll
        for (int ui = 0; ui < 4; ++ui) {
            int u = ((ui >> 1) << 3) + 2 * a + (ui & 1);
            int b_row = bg * 128 + mt * 16 + (lane >> 2) + rs * 8;
            int j = hs * 16 + u;
            outC[b_row * 256 + j] = cs0[rs][ui];
            outC[Bsz * NH + b_row * 256 + j] = cs1[rs][ui];
        }
}

// -------------------- decoded head --------------------
__global__ void decode_kernel(const float* __restrict__ fcw, const float* __restrict__ fcb,
                              const float* __restrict__ decw, const float* __restrict__ decb,
                              float* __restrict__ out) {
    int b = blockIdx.x * blockDim.x + threadIdx.x;
    if (b >= Bsz) return;
    const float* h1 = out + 2 * Bsz + Bsz * NH + b * 256;
    float d0 = decb[0], d1 = decb[1];
#pragma unroll 1
    for (int m = 0; m < 10; ++m) {
        float s = fcb[m];
        for (int j = 0; j < 256; ++j) s = fmaf(h1[j], fcw[m * 256 + j], s);
        s = fmaxf(s, 0.f);
        d0 = fmaf(s, decw[m], d0);
        d1 = fmaf(s, decw[10 + m], d1);
    }
    out[b] = d0;
    out[Bsz + b] = d1;
}

// -------------------- launch --------------------
extern "C" void kernel_launch(void* const* d_in, const int* in_sizes, int n_in,
                              void* d_out, int out_size) {
    const int*   input = (const int*)  d_in[0];
    const float* h0    = (const float*)d_in[1];
    const float* emb   = (const float*)d_in[3];
    const float* fcw   = (const float*)d_in[4];
    const float* fcb   = (const float*)d_in[5];
    const float* decw  = (const float*)d_in[6];
    const float* decb  = (const float*)d_in[7];
    float* out = (float*)d_out;

    cudaFuncSetAttribute(lstm_kernel, cudaFuncAttributeMaxDynamicSharedMemorySize, SMEM_SZ);

    unsigned nX = Tst * NBG * 8 * 2 * 32;
    pack_x_kernel<<<(nX + 255) / 256, 256>>>(input, emb);
    int nW = NGS * NBLK * 512 + 2048;
    prep_w_kernel<<<(nW + 255) / 256, 256>>>(
        (const float*)d_in[8], (const float*)d_in[9], (const float*)d_in[10], (const float*)d_in[11],
        (const float*)d_in[12], (const float*)d_in[13], (const float*)d_in[14], (const float*)d_in[15]);
    unsigned nH = 2 * NBG * 8 * 16 * 32;
    init_h_kernel<<<(nH + 255) / 256, 256>>>(h0);
    lstm_kernel<<<NCTA, 256, SMEM_SZ>>>(h0, (const float*)d_in[2], out);
    decode_kernel<<<(Bsz + 255) / 256, 256>>>(fcw, fcb, decw, decb, out);
}

// round 11
// speedup vs baseline: 2.1425x; 1.0079x over previous
#include <cuda_runtime.h>
#include <cuda_bf16.h>

#define Bsz 1024
#define Tst 300
#define NH  256
#define NBG 8      // legacy fragment-array batch groups (128 rows)
#define NGR 16     // runtime groups (64 rows each)
#define NGS 16     // gate-slice CTAs per group
#define NCTA 128

#define BLK_W0XH 0
#define BLK_W0XL 2
#define BLK_W0HH 4
#define BLK_W0HL 20
#define BLK_W1XH 36
#define BLK_W1XL 52
#define BLK_W1HH 68
#define BLK_W1HL 84
#define NBLK     100
#define SMEM_SZ  (NBLK * 2048 + 512)

// -------------------- device scratch --------------------
__device__ unsigned g_Wfrag[(size_t)NGS * NBLK * 512];
__device__ float    g_biasP[2 * NGS * 64];
__device__ unsigned g_Xfrag[(size_t)Tst * NBG * 8 * 2 * 256];
__device__ unsigned g_Hfrag[2 * 2 * NBG * 8 * 16 * 256];
__device__ unsigned g_cntA[NGR], g_genA[NGR];
__device__ unsigned g_cntB[NGR], g_genB[NGR];

__device__ __forceinline__ size_t hoff(int l, int buf, int bg8, int mt8, int ch) {
    return ((((((size_t)(l * 2 + buf)) * NBG + bg8) * 8 + mt8) * 16 + ch) * 256);
}
__device__ __forceinline__ size_t xoff(int t, int bg8, int mt8, int c) {
    return ((((size_t)t * NBG + bg8) * 8 + mt8) * 2 + c) * 256;
}

__device__ __forceinline__ void split2(float v0, float v1, unsigned& hi, unsigned& lo) {
    __nv_bfloat16 h0 = __float2bfloat16(v0), h1 = __float2bfloat16(v1);
    __nv_bfloat16 l0 = __float2bfloat16(v0 - __bfloat162float(h0));
    __nv_bfloat16 l1 = __float2bfloat16(v1 - __bfloat162float(h1));
    hi = (unsigned)__bfloat16_as_ushort(h0) | ((unsigned)__bfloat16_as_ushort(h1) << 16);
    lo = (unsigned)__bfloat16_as_ushort(l0) | ((unsigned)__bfloat16_as_ushort(l1) << 16);
}
__device__ __forceinline__ float sigm(float x) { return 1.f / (1.f + __expf(-x)); }
__device__ __forceinline__ float tanh_f(float x) {
    x = fminf(fmaxf(x, -15.f), 15.f);
    float e = __expf(2.f * x);
    return __fdividef(e - 1.f, e + 1.f);
}

__device__ __forceinline__ void mma4(float* d, const unsigned* a, unsigned b0, unsigned b1) {
    asm volatile("mma.sync.aligned.m16n8k16.row.col.f32.bf16.bf16.f32 "
        "{%0,%1,%2,%3}, {%4,%5,%6,%7}, {%8,%9}, {%0,%1,%2,%3};"
        : "+f"(d[0]), "+f"(d[1]), "+f"(d[2]), "+f"(d[3])
        : "r"(a[0]), "r"(a[1]), "r"(a[2]), "r"(a[3]), "r"(b0), "r"(b1));
}

// -------------------- x gather --------------------
__device__ __forceinline__ float fetch_x(const int* __restrict__ input,
                                         const float* __restrict__ emb,
                                         int t, int b, int k) {
    if (k >= 25) return 0.f;
    long flat = (long)t * (Bsz * 25) + b * 25 + k;
    int s = (int)(flat / (Bsz * 300));
    int rr = (int)(flat % (Bsz * 300));
    int bb = rr / 300, e = rr % 300;
    return emb[(long)input[bb * 25 + s] * 300 + e];
}

// -------------------- prep kernels --------------------
__global__ void pack_x_kernel(const int* __restrict__ input, const float* __restrict__ emb) {
    unsigned idx = blockIdx.x * blockDim.x + threadIdx.x;
    if (idx >= (unsigned)Tst * NBG * 8 * 2 * 32) return;
    int lane = idx & 31;
    unsigned r = idx >> 5;
    int c = r & 1; r >>= 1;
    int mt = r & 7; r >>= 3;
    int bg = r & 7;
    int t = r >> 3;
    unsigned ohi[4], olo[4];
#pragma unroll
    for (int reg = 0; reg < 4; ++reg) {
        int row = mt * 16 + (lane >> 2) + (reg & 1) * 8;
        int b = bg * 128 + row;
        int k = c * 16 + ((reg >> 1) & 1) * 8 + 2 * (lane & 3);
        float v0 = fetch_x(input, emb, t, b, k);
        float v1 = fetch_x(input, emb, t, b, k + 1);
        split2(v0, v1, ohi[reg], olo[reg]);
    }
    unsigned* base = g_Xfrag + (size_t)(idx >> 5) * 256;
    *(uint4*)(base + lane * 4)       = make_uint4(ohi[0], ohi[1], ohi[2], ohi[3]);
    *(uint4*)(base + 128 + lane * 4) = make_uint4(olo[0], olo[1], olo[2], olo[3]);
}

__global__ void prep_w_kernel(
    const float* __restrict__ Wih0, const float* __restrict__ Whh0,
    const float* __restrict__ bih0, const float* __restrict__ bhh0,
    const float* __restrict__ Wih1, const float* __restrict__ Whh1,
    const float* __restrict__ bih1, const float* __restrict__ bhh1) {
    const int NWF = NGS * NBLK * 512;
    int idx = blockIdx.x * blockDim.x + threadIdx.x;
    if (idx < NWF) {
        int hs = idx / (NBLK * 512);
        int rem = idx % (NBLK * 512);
        int blk = rem / 512, q = rem % 512;
        int L = (q >> 2) & 31, w = q & 3, i = q >> 7;
        int j = i * 4 + w;
        int nt = j >> 1, regb = j & 1;
        int mat, ch, hl;
        if (blk < 4) { mat = 0; hl = blk >> 1; ch = blk & 1; }
        else { int bb = blk - 4; mat = 1 + bb / 32; int cc = bb % 32; hl = cc >> 4; ch = cc & 15; }
        int k = ch * 16 + regb * 8 + 2 * (L & 3);
        int nl = nt * 8 + (L >> 2);
        int r = (nl >> 4) * 256 + hs * 16 + (nl & 15);
        float v0 = 0.f, v1 = 0.f;
        if (mat == 0) {
            if (k < 25)     v0 = Wih0[r * 25 + k];
            if (k + 1 < 25) v1 = Wih0[r * 25 + k + 1];
        } else if (mat == 1) { v0 = Whh0[r * 256 + k]; v1 = Whh0[r * 256 + k + 1]; }
        else if (mat == 2)   { v0 = Wih1[r * 256 + k]; v1 = Wih1[r * 256 + k + 1]; }
        else                 { v0 = Whh1[r * 256 + k]; v1 = Whh1[r * 256 + k + 1]; }
        unsigned hi, lo;
        split2(v0, v1, hi, lo);
        g_Wfrag[idx] = hl ? lo : hi;
    } else if (idx < NWF + 2048) {
        int i2 = idx - NWF;
        int l = i2 >> 10, rest = i2 & 1023, hs = rest >> 6, nl = rest & 63;
        int r = (nl >> 4) * 256 + hs * 16 + (nl & 15);
        g_biasP[i2] = (l == 0) ? (bih0[r] + bhh0[r]) : (bih1[r] + bhh1[r]);
    }
}

__global__ void init_h_kernel(const float* __restrict__ h0in) {
    unsigned idx = blockIdx.x * blockDim.x + threadIdx.x;
    if (idx < NGR) {
        g_cntA[idx] = 0; g_genA[idx] = 0;
        g_cntB[idx] = 0; g_genB[idx] = 0;
    }
    if (idx >= 2u * NBG * 8 * 16 * 32) return;
    int lane = idx & 31;
    unsigned r = idx >> 5;
    int ch = r & 15; r >>= 4;
    int mt = r & 7; r >>= 3;
    int bg = r & 7;
    int l = r >> 3;
    unsigned ohi[4], olo[4];
#pragma unroll
    for (int reg = 0; reg < 4; ++reg) {
        int row = mt * 16 + (lane >> 2) + (reg & 1) * 8;
        int b = bg * 128 + row;
        int j = ch * 16 + ((reg >> 1) & 1) * 8 + 2 * (lane & 3);
        const float* src = h0in + (size_t)l * (Bsz * NH) + b * 256 + j;
        split2(src[0], src[1], ohi[reg], olo[reg]);
    }
    unsigned* base = g_Hfrag + hoff(l, 0, bg, mt, ch);
    *(uint4*)(base + lane * 4)       = make_uint4(ohi[0], ohi[1], ohi[2], ohi[3]);
    *(uint4*)(base + 128 + lane * 4) = make_uint4(olo[0], olo[1], olo[2], olo[3]);
}

// -------------------- per-job (half-CTA) barrier --------------------
__device__ __forceinline__ void jbar(int jb) {
    asm volatile("bar.sync %0, 128;" :: "r"(jb + 1) : "memory");
}
__device__ __forceinline__ void bar_arrive(unsigned* cnt, unsigned* gen, int grp,
                                           int jb, bool lead) {
    jbar(jb);
    if (lead) {
        __threadfence();
        unsigned old = atomicAdd(&cnt[grp], 1u);
        if (old == NGS - 1) {
            atomicExch(&cnt[grp], 0u);
            __threadfence();
            atomicAdd(&gen[grp], 1u);
        }
    }
}
__device__ __forceinline__ void bar_wait(unsigned* gen, int grp, unsigned target,
                                         int jb, bool lead) {
    if (lead) {
        volatile unsigned* gp = gen + grp;
        while (*gp < target) __nanosleep(32);
        __threadfence();
    }
    jbar(jb);
}

// -------------------- pipelined chunk pieces --------------------
struct AF { unsigned h[4], l[4]; };

__device__ __forceinline__ AF lda(const unsigned* __restrict__ A, int lane) {
    AF f;
    uint4 a = __ldcg((const uint4*)(A + lane * 4));
    uint4 b = __ldcg((const uint4*)(A + 128 + lane * 4));
    f.h[0]=a.x; f.h[1]=a.y; f.h[2]=a.z; f.h[3]=a.w;
    f.l[0]=b.x; f.l[1]=b.y; f.l[2]=b.z; f.l[3]=b.w;
    return f;
}

__device__ __forceinline__ void compute_chunk(float (&acc)[8][4], const AF& f,
        const uint4* __restrict__ smq, int blkh, int blkl, int lane) {
    const uint4* WH = smq + blkh * 128;
    uint4 q0 = WH[lane], q1 = WH[32 + lane], q2 = WH[64 + lane], q3 = WH[96 + lane];
    unsigned wb[16] = {q0.x,q0.y,q0.z,q0.w, q1.x,q1.y,q1.z,q1.w,
                       q2.x,q2.y,q2.z,q2.w, q3.x,q3.y,q3.z,q3.w};
#pragma unroll
    for (int nt = 0; nt < 8; ++nt) mma4(acc[nt], f.h, wb[2*nt], wb[2*nt+1]);
#pragma unroll
    for (int nt = 0; nt < 8; ++nt) mma4(acc[nt], f.l, wb[2*nt], wb[2*nt+1]);
    const uint4* WL = smq + blkl * 128;
    q0 = WL[lane]; q1 = WL[32 + lane]; q2 = WL[64 + lane]; q3 = WL[96 + lane];
    unsigned wc[16] = {q0.x,q0.y,q0.z,q0.w, q1.x,q1.y,q1.z,q1.w,
                       q2.x,q2.y,q2.z,q2.w, q3.x,q3.y,q3.z,q3.w};
#pragma unroll
    for (int nt = 0; nt < 8; ++nt) mma4(acc[nt], f.h, wc[2*nt], wc[2*nt+1]);
}

// -------------------- epilogue --------------------
__device__ __forceinline__ void epilogue(int l, int pnew, int bg8, int mt8, int hs, int lane,
        float (&acc)[8][4], float (&cs)[2][4], const float* __restrict__ bias_s,
        float* __restrict__ outH) {
    int a = lane & 3;
    unsigned* base = g_Hfrag + hoff(l, pnew, bg8, mt8, hs);
    int lanep = (lane >> 2) * 4 + a;
#pragma unroll
    for (int rs = 0; rs < 2; ++rs) {
        float hv[4];
#pragma unroll
        for (int ui = 0; ui < 4; ++ui) {
            int u = ((ui >> 1) << 3) + 2 * a + (ui & 1);
            int sub = ui >> 1, dr = rs * 2 + (ui & 1);
            float gi = acc[sub][dr]     + bias_s[l * 64 + u];
            float gf = acc[2 + sub][dr] + bias_s[l * 64 + 16 + u];
            float gg = acc[4 + sub][dr] + bias_s[l * 64 + 32 + u];
            float go = acc[6 + sub][dr] + bias_s[l * 64 + 48 + u];
            float c = fmaf(sigm(gf), cs[rs][ui], sigm(gi) * tanh_f(gg));
            cs[rs][ui] = c;
            hv[ui] = sigm(go) * tanh_f(c);
        }
#pragma unroll
        for (int pp = 0; pp < 2; ++pp) {
            unsigned hi, lo;
            split2(hv[2 * pp], hv[2 * pp + 1], hi, lo);
            int reg = rs + 2 * pp;
            base[lanep * 4 + reg]       = hi;
            base[128 + lanep * 4 + reg] = lo;
        }
        if (outH) {
            int b_row = bg8 * 128 + mt8 * 16 + (lane >> 2) + rs * 8;
#pragma unroll
            for (int ui = 0; ui < 4; ++ui) {
                int u = ((ui >> 1) << 3) + 2 * a + (ui & 1);
                outH[(size_t)l * Bsz * NH + b_row * 256 + hs * 16 + u] = hv[ui];
            }
        }
    }
}

// -------------------- main persistent kernel --------------------
// 128 CTAs; each CTA runs TWO independent 64-row recurrence jobs (4 warps each)
// sharing one W SMEM image. Jobs interleave on the SMSPs for latency hiding.
__global__ void __launch_bounds__(256, 1) lstm_kernel(
    const float* __restrict__ h0in, const float* __restrict__ c0in,
    float* __restrict__ out) {
    extern __shared__ uint4 smq[];
    const int tid = threadIdx.x, lane = tid & 31, wid = tid >> 5;
    const int jb = wid >> 2;          // job 0/1
    const int mt = wid & 3;           // warp tile within job (16 rows each)
    const int bgp = blockIdx.x >> 4;  // 0..7
    const int hs = blockIdx.x & 15;
    const int bg = bgp + jb * 8;      // runtime group 0..15 (64 rows)
    const int bg8 = bg >> 1;          // legacy fragment indices
    const int mt8 = (bg & 1) * 4 + mt;
    const bool lead = ((tid & 127) == 0);
    const int a = lane & 3;

    const uint4* wsrc = (const uint4*)g_Wfrag + (size_t)hs * (NBLK * 128);
    for (int i = tid; i < NBLK * 128; i += 256) smq[i] = wsrc[i];
    float* bias_s = (float*)(smq + NBLK * 128);
    if (tid < 128) bias_s[tid] = g_biasP[(tid >> 6) * 1024 + hs * 64 + (tid & 63)];
    __syncthreads();

    float cs0[2][4], cs1[2][4];
#pragma unroll
    for (int rs = 0; rs < 2; ++rs)
#pragma unroll
        for (int ui = 0; ui < 4; ++ui) {
            int u = ((ui >> 1) << 3) + 2 * a + (ui & 1);
            int b_row = bg8 * 128 + mt8 * 16 + (lane >> 2) + rs * 8;
            int j = hs * 16 + u;
            cs0[rs][ui] = c0in[b_row * 256 + j];
            cs1[rs][ui] = c0in[Bsz * NH + b_row * 256 + j];
        }

    float* outH = out + 2 * Bsz;
    int p = 0;
#pragma unroll 1
    for (int t = 0; t < Tst; ++t) {
        float acc[8][4];
#pragma unroll
        for (int nt = 0; nt < 8; ++nt)
#pragma unroll
            for (int d = 0; d < 4; ++d) acc[nt][d] = 0.f;

        // ---- L0: x chunks + W0h*h0[p], depth-2 prefetch ----
        {
            AF cur = lda(g_Xfrag + xoff(t, bg8, mt8, 0), lane);
            AF nxt = lda(g_Xfrag + xoff(t, bg8, mt8, 1), lane);
            compute_chunk(acc, cur, smq, BLK_W0XH + 0, BLK_W0XL + 0, lane);
            cur = nxt;
            nxt = lda(g_Hfrag + hoff(0, p, bg8, mt8, 0), lane);
            compute_chunk(acc, cur, smq, BLK_W0XH + 1, BLK_W0XL + 1, lane);
#pragma unroll 1
            for (int c = 0; c < 16; ++c) {
                cur = nxt;
                if (c < 15) nxt = lda(g_Hfrag + hoff(0, p, bg8, mt8, c + 1), lane);
                compute_chunk(acc, cur, smq, BLK_W0HH + c, BLK_W0HL + c, lane);
            }
        }
        epilogue(0, 1 - p, bg8, mt8, hs, lane, acc, cs0, bias_s, (t == Tst - 1) ? outH : nullptr);
        bar_arrive(g_cntA, g_genA, bg, jb, lead);

        bar_wait(g_genB, bg, (unsigned)t, jb, lead);   // h1[p] from step t-1 visible

#pragma unroll
        for (int nt = 0; nt < 8; ++nt)
#pragma unroll
            for (int d = 0; d < 4; ++d) acc[nt][d] = 0.f;

        // ---- L1 part A: W1h*h1[p] ----
        {
            AF cur = lda(g_Hfrag + hoff(1, p, bg8, mt8, 0), lane);
            AF nxt = cur;
#pragma unroll 1
            for (int c = 0; c < 16; ++c) {
                if (c < 15) nxt = lda(g_Hfrag + hoff(1, p, bg8, mt8, c + 1), lane);
                compute_chunk(acc, cur, smq, BLK_W1HH + c, BLK_W1HL + c, lane);
                cur = nxt;
            }
        }
        bar_wait(g_genA, bg, (unsigned)(t + 1), jb, lead);  // everyone's h0[1-p]

        // ---- L1 part B: W1x*h0[1-p] ----
        {
            AF cur = lda(g_Hfrag + hoff(0, 1 - p, bg8, mt8, 0), lane);
            AF nxt = cur;
#pragma unroll 1
            for (int c = 0; c < 16; ++c) {
                if (c < 15) nxt = lda(g_Hfrag + hoff(0, 1 - p, bg8, mt8, c + 1), lane);
                compute_chunk(acc, cur, smq, BLK_W1XH + c, BLK_W1XL + c, lane);
                cur = nxt;
            }
        }
        epilogue(1, 1 - p, bg8, mt8, hs, lane, acc, cs1, bias_s, (t == Tst - 1) ? outH : nullptr);
        bar_arrive(g_cntB, g_genB, bg, jb, lead);
        p ^= 1;
    }

    float* outC = out + 2 * Bsz + 2 * Bsz * NH;
#pragma unroll
    for (int rs = 0; rs < 2; ++rs)
#pragma unroll
        for (int ui = 0; ui < 4; ++ui) {
            int u = ((ui >> 1) << 3) + 2 * a + (ui & 1);
            int b_row = bg8 * 128 + mt8 * 16 + (lane >> 2) + rs * 8;
            int j = hs * 16 + u;
            outC[b_row * 256 + j] = cs0[rs][ui];
            outC[Bsz * NH + b_row * 256 + j] = cs1[rs][ui];
        }
}

// -------------------- decoded head --------------------
__global__ void decode_kernel(const float* __restrict__ fcw, const float* __restrict__ fcb,
                              const float* __restrict__ decw, const float* __restrict__ decb,
                              float* __restrict__ out) {
    int b = blockIdx.x * blockDim.x + threadIdx.x;
    if (b >= Bsz) return;
    const float* h1 = out + 2 * Bsz + Bsz * NH + b * 256;
    float d0 = decb[0], d1 = decb[1];
#pragma unroll 1
    for (int m = 0; m < 10; ++m) {
        float s = fcb[m];
        for (int j = 0; j < 256; ++j) s = fmaf(h1[j], fcw[m * 256 + j], s);
        s = fmaxf(s, 0.f);
        d0 = fmaf(s, decw[m], d0);
        d1 = fmaf(s, decw[10 + m], d1);
    }
    out[b] = d0;
    out[Bsz + b] = d1;
}

// -------------------- launch --------------------
extern "C" void kernel_launch(void* const* d_in, const int* in_sizes, int n_in,
                              void* d_out, int out_size) {
    const int*   input = (const int*)  d_in[0];
    const float* h0    = (const float*)d_in[1];
    const float* emb   = (const float*)d_in[3];
    const float* fcw   = (const float*)d_in[4];
    const float* fcb   = (const float*)d_in[5];
    const float* decw  = (const float*)d_in[6];
    const float* decb  = (const float*)d_in[7];
    float* out = (float*)d_out;

    cudaFuncSetAttribute(lstm_kernel, cudaFuncAttributeMaxDynamicSharedMemorySize, SMEM_SZ);

    unsigned nX = Tst * NBG * 8 * 2 * 32;
    pack_x_kernel<<<(nX + 255) / 256, 256>>>(input, emb);
    int nW = NGS * NBLK * 512 + 2048;
    prep_w_kernel<<<(nW + 255) / 256, 256>>>(
        (const float*)d_in[8], (const float*)d_in[9], (const float*)d_in[10], (const float*)d_in[11],
        (const float*)d_in[12], (const float*)d_in[13], (const float*)d_in[14], (const float*)d_in[15]);
    unsigned nH = 2 * NBG * 8 * 16 * 32;
    init_h_kernel<<<(nH + 255) / 256, 256>>>(h0);
    lstm_kernel<<<NCTA, 256, SMEM_SZ>>>(h0, (const float*)d_in[2], out);
    decode_kernel<<<(Bsz + 255) / 256, 256>>>(fcw, fcb, decw, decb, out);
}

// round 12
// speedup vs baseline: 2.2567x; 1.0533x over previous
#include <cuda_runtime.h>
#include <cuda_bf16.h>

#define Bsz 1024
#define Tst 300
#define NH  256
#define NBG 8      // batch groups (128 rows)
#define NGS 16     // gate-slice CTAs per group (64 gate cols each)
#define NCTA 128

#define BLK_W0XH 0
#define BLK_W0XL 2
#define BLK_W0HH 4
#define BLK_W0HL 20
#define BLK_W1XH 36
#define BLK_W1XL 52
#define BLK_W1HH 68
#define BLK_W1HL 84
#define NBLK     100
#define SMEM_SZ  (NBLK * 2048 + 512)

// -------------------- device scratch --------------------
__device__ unsigned g_Wfrag[(size_t)NGS * NBLK * 512];
__device__ float    g_biasP[2 * NGS * 64];
__device__ unsigned g_Xfrag[(size_t)Tst * NBG * 8 * 2 * 256];
__device__ unsigned g_Hfrag[2 * 2 * NBG * 8 * 16 * 256];
__device__ unsigned g_cntA[NBG], g_genA[NBG];
__device__ unsigned g_cntB[NBG], g_genB[NBG];

__device__ __forceinline__ size_t hoff(int l, int buf, int bg, int mt, int ch) {
    return ((((((size_t)(l * 2 + buf)) * NBG + bg) * 8 + mt) * 16 + ch) * 256);
}
__device__ __forceinline__ size_t xoff(int t, int bg, int mt, int c) {
    return ((((size_t)t * NBG + bg) * 8 + mt) * 2 + c) * 256;
}

__device__ __forceinline__ void split2(float v0, float v1, unsigned& hi, unsigned& lo) {
    __nv_bfloat16 h0 = __float2bfloat16(v0), h1 = __float2bfloat16(v1);
    __nv_bfloat16 l0 = __float2bfloat16(v0 - __bfloat162float(h0));
    __nv_bfloat16 l1 = __float2bfloat16(v1 - __bfloat162float(h1));
    hi = (unsigned)__bfloat16_as_ushort(h0) | ((unsigned)__bfloat16_as_ushort(h1) << 16);
    lo = (unsigned)__bfloat16_as_ushort(l0) | ((unsigned)__bfloat16_as_ushort(l1) << 16);
}
__device__ __forceinline__ float sigm(float x) { return 1.f / (1.f + __expf(-x)); }
__device__ __forceinline__ float tanh_f(float x) {
    x = fminf(fmaxf(x, -15.f), 15.f);
    float e = __expf(2.f * x);
    return __fdividef(e - 1.f, e + 1.f);
}

__device__ __forceinline__ void mma4(float* d, const unsigned* a, unsigned b0, unsigned b1) {
    asm volatile("mma.sync.aligned.m16n8k16.row.col.f32.bf16.bf16.f32 "
        "{%0,%1,%2,%3}, {%4,%5,%6,%7}, {%8,%9}, {%0,%1,%2,%3};"
        : "+f"(d[0]), "+f"(d[1]), "+f"(d[2]), "+f"(d[3])
        : "r"(a[0]), "r"(a[1]), "r"(a[2]), "r"(a[3]), "r"(b0), "r"(b1));
}

// -------------------- x gather --------------------
__device__ __forceinline__ float fetch_x(const int* __restrict__ input,
                                         const float* __restrict__ emb,
                                         int t, int b, int k) {
    if (k >= 25) return 0.f;
    long flat = (long)t * (Bsz * 25) + b * 25 + k;
    int s = (int)(flat / (Bsz * 300));
    int rr = (int)(flat % (Bsz * 300));
    int bb = rr / 300, e = rr % 300;
    return emb[(long)input[bb * 25 + s] * 300 + e];
}

// -------------------- prep kernels --------------------
__global__ void pack_x_kernel(const int* __restrict__ input, const float* __restrict__ emb) {
    unsigned idx = blockIdx.x * blockDim.x + threadIdx.x;
    if (idx >= (unsigned)Tst * NBG * 8 * 2 * 32) return;
    int lane = idx & 31;
    unsigned r = idx >> 5;
    int c = r & 1; r >>= 1;
    int mt = r & 7; r >>= 3;
    int bg = r & 7;
    int t = r >> 3;
    unsigned ohi[4], olo[4];
#pragma unroll
    for (int reg = 0; reg < 4; ++reg) {
        int row = mt * 16 + (lane >> 2) + (reg & 1) * 8;
        int b = bg * 128 + row;
        int k = c * 16 + ((reg >> 1) & 1) * 8 + 2 * (lane & 3);
        float v0 = fetch_x(input, emb, t, b, k);
        float v1 = fetch_x(input, emb, t, b, k + 1);
        split2(v0, v1, ohi[reg], olo[reg]);
    }
    unsigned* base = g_Xfrag + (size_t)(idx >> 5) * 256;
    *(uint4*)(base + lane * 4)       = make_uint4(ohi[0], ohi[1], ohi[2], ohi[3]);
    *(uint4*)(base + 128 + lane * 4) = make_uint4(olo[0], olo[1], olo[2], olo[3]);
}

// W block layout (512 u32 per block, 2KB), ns-major halves:
//   u32 index q = ns*256 + k2*128 + L*4 + m   (L = lane, m in [0,4))
//   gate g = k2*2 + (m>>1), regb = m&1, nt_global = g*2 + ns
//   nl = nt_global*8 + (L>>2),  k = ch*16 + regb*8 + 2*(L&3)
__global__ void prep_w_kernel(
    const float* __restrict__ Wih0, const float* __restrict__ Whh0,
    const float* __restrict__ bih0, const float* __restrict__ bhh0,
    const float* __restrict__ Wih1, const float* __restrict__ Whh1,
    const float* __restrict__ bih1, const float* __restrict__ bhh1) {
    const int NWF = NGS * NBLK * 512;
    int idx = blockIdx.x * blockDim.x + threadIdx.x;
    if (idx < NWF) {
        int hs = idx / (NBLK * 512);
        int rem = idx % (NBLK * 512);
        int blk = rem / 512, q = rem % 512;
        int ns = q >> 8, k2 = (q >> 7) & 1, L = (q >> 2) & 31, m = q & 3;
        int g = k2 * 2 + (m >> 1), regb = m & 1;
        int nt = g * 2 + ns;
        int mat, ch, hl;
        if (blk < 4) { mat = 0; hl = blk >> 1; ch = blk & 1; }
        else { int bb = blk - 4; mat = 1 + bb / 32; int cc = bb % 32; hl = cc >> 4; ch = cc & 15; }
        int k = ch * 16 + regb * 8 + 2 * (L & 3);
        int nl = nt * 8 + (L >> 2);
        int r = (nl >> 4) * 256 + hs * 16 + (nl & 15);
        float v0 = 0.f, v1 = 0.f;
        if (mat == 0) {
            if (k < 25)     v0 = Wih0[r * 25 + k];
            if (k + 1 < 25) v1 = Wih0[r * 25 + k + 1];
        } else if (mat == 1) { v0 = Whh0[r * 256 + k]; v1 = Whh0[r * 256 + k + 1]; }
        else if (mat == 2)   { v0 = Wih1[r * 256 + k]; v1 = Wih1[r * 256 + k + 1]; }
        else                 { v0 = Whh1[r * 256 + k]; v1 = Whh1[r * 256 + k + 1]; }
        unsigned hi, lo;
        split2(v0, v1, hi, lo);
        g_Wfrag[idx] = hl ? lo : hi;
    } else if (idx < NWF + 2048) {
        int i2 = idx - NWF;
        int l = i2 >> 10, rest = i2 & 1023, hs = rest >> 6, nl = rest & 63;
        int r = (nl >> 4) * 256 + hs * 16 + (nl & 15);
        g_biasP[i2] = (l == 0) ? (bih0[r] + bhh0[r]) : (bih1[r] + bhh1[r]);
    }
}

__global__ void init_h_kernel(const float* __restrict__ h0in) {
    unsigned idx = blockIdx.x * blockDim.x + threadIdx.x;
    if (idx < NBG) {
        g_cntA[idx] = 0; g_genA[idx] = 0;
        g_cntB[idx] = 0; g_genB[idx] = 0;
    }
    if (idx >= 2u * NBG * 8 * 16 * 32) return;
    int lane = idx & 31;
    unsigned r = idx >> 5;
    int ch = r & 15; r >>= 4;
    int mt = r & 7; r >>= 3;
    int bg = r & 7;
    int l = r >> 3;
    unsigned ohi[4], olo[4];
#pragma unroll
    for (int reg = 0; reg < 4; ++reg) {
        int row = mt * 16 + (lane >> 2) + (reg & 1) * 8;
        int b = bg * 128 + row;
        int j = ch * 16 + ((reg >> 1) & 1) * 8 + 2 * (lane & 3);
        const float* src = h0in + (size_t)l * (Bsz * NH) + b * 256 + j;
        split2(src[0], src[1], ohi[reg], olo[reg]);
    }
    unsigned* base = g_Hfrag + hoff(l, 0, bg, mt, ch);
    *(uint4*)(base + lane * 4)       = make_uint4(ohi[0], ohi[1], ohi[2], ohi[3]);
    *(uint4*)(base + 128 + lane * 4) = make_uint4(olo[0], olo[1], olo[2], olo[3]);
}

// -------------------- split group barrier --------------------
__device__ __forceinline__ void bar_arrive(unsigned* cnt, unsigned* gen, int grp) {
    __syncthreads();
    if (threadIdx.x == 0) {
        __threadfence();
        unsigned old = atomicAdd(&cnt[grp], 1u);
        if (old == NGS - 1) {
            atomicExch(&cnt[grp], 0u);
            __threadfence();
            atomicAdd(&gen[grp], 1u);
        }
    }
}
__device__ __forceinline__ void bar_wait(unsigned* gen, int grp, unsigned target) {
    if (threadIdx.x == 0) {
        volatile unsigned* gp = gen + grp;
        while (*gp < target) __nanosleep(32);
        __threadfence();
    }
    __syncthreads();
}

// -------------------- pipelined chunk pieces --------------------
struct AF { unsigned h[4], l[4]; };

__device__ __forceinline__ AF lda(const unsigned* __restrict__ A, int lane) {
    AF f;
    uint4 a = __ldcg((const uint4*)(A + lane * 4));
    uint4 b = __ldcg((const uint4*)(A + 128 + lane * 4));
    f.h[0]=a.x; f.h[1]=a.y; f.h[2]=a.z; f.h[3]=a.w;
    f.l[0]=b.x; f.l[1]=b.y; f.l[2]=b.z; f.l[3]=b.w;
    return f;
}

// Each warp computes its ns-half (32 gate cols = 4 MMA tiles = 4 gates).
__device__ __forceinline__ void compute_chunk(float (&acc)[4][4], const AF& f,
        const uint4* __restrict__ smq, int blkh, int blkl, int lane, int ns) {
    const uint4* WH = smq + blkh * 128 + ns * 64;
    uint4 q0 = WH[lane], q1 = WH[32 + lane];
    unsigned wb[8] = {q0.x,q0.y,q0.z,q0.w, q1.x,q1.y,q1.z,q1.w};
#pragma unroll
    for (int g = 0; g < 4; ++g) mma4(acc[g], f.h, wb[2*g], wb[2*g+1]);
#pragma unroll
    for (int g = 0; g < 4; ++g) mma4(acc[g], f.l, wb[2*g], wb[2*g+1]);
    const uint4* WL = smq + blkl * 128 + ns * 64;
    q0 = WL[lane]; q1 = WL[32 + lane];
    unsigned wc[8] = {q0.x,q0.y,q0.z,q0.w, q1.x,q1.y,q1.z,q1.w};
#pragma unroll
    for (int g = 0; g < 4; ++g) mma4(acc[g], f.h, wc[2*g], wc[2*g+1]);
}

// -------------------- epilogue --------------------
__device__ __forceinline__ void epilogue(int l, int pnew, int bg, int mt, int hs,
        int lane, int ns,
        float (&acc)[4][4], float (&cs)[2][2], const float* __restrict__ bias_s,
        float* __restrict__ outH) {
    int a = lane & 3;
    unsigned* base = g_Hfrag + hoff(l, pnew, bg, mt, hs);
    int lanep = (lane >> 2) * 4 + a;
#pragma unroll
    for (int rs = 0; rs < 2; ++rs) {
        float hv[2];
#pragma unroll
        for (int ui = 0; ui < 2; ++ui) {
            int u = ns * 8 + 2 * a + ui;
            int dr = rs * 2 + ui;
            float gi = acc[0][dr] + bias_s[l * 64 + u];
            float gf = acc[1][dr] + bias_s[l * 64 + 16 + u];
            float gg = acc[2][dr] + bias_s[l * 64 + 32 + u];
            float go = acc[3][dr] + bias_s[l * 64 + 48 + u];
            float c = fmaf(sigm(gf), cs[rs][ui], sigm(gi) * tanh_f(gg));
            cs[rs][ui] = c;
            hv[ui] = sigm(go) * tanh_f(c);
        }
        unsigned hi, lo;
        split2(hv[0], hv[1], hi, lo);
        base[lanep * 4 + rs + 2 * ns]       = hi;
        base[128 + lanep * 4 + rs + 2 * ns] = lo;
        if (outH) {
            int b_row = bg * 128 + mt * 16 + (lane >> 2) + rs * 8;
#pragma unroll
            for (int ui = 0; ui < 2; ++ui)
                outH[(size_t)l * Bsz * NH + b_row * 256 + hs * 16 + ns * 8 + 2 * a + ui] = hv[ui];
        }
    }
}

// -------------------- main persistent kernel --------------------
// 128 CTAs x 512 threads (16 warps). Warp (mt, ns): 16 rows x 32 gate cols.
// 4 warps/SMSP for latency hiding; same W SMEM image; same FP order as R10.
__global__ void __launch_bounds__(512, 1) lstm_kernel(
    const float* __restrict__ h0in, const float* __restrict__ c0in,
    float* __restrict__ out) {
    extern __shared__ uint4 smq[];
    const int tid = threadIdx.x, lane = tid & 31, wid = tid >> 5;
    const int mt = wid & 7;           // M tile (16 rows)
    const int ns = wid >> 3;          // N half (32 cols)
    const int bg = blockIdx.x >> 4;
    const int hs = blockIdx.x & 15;
    const int a = lane & 3;

    const uint4* wsrc = (const uint4*)g_Wfrag + (size_t)hs * (NBLK * 128);
    for (int i = tid; i < NBLK * 128; i += 512) smq[i] = wsrc[i];
    float* bias_s = (float*)(smq + NBLK * 128);
    if (tid < 128) bias_s[tid] = g_biasP[(tid >> 6) * 1024 + hs * 64 + (tid & 63)];
    __syncthreads();

    float cs0[2][2], cs1[2][2];
#pragma unroll
    for (int rs = 0; rs < 2; ++rs)
#pragma unroll
        for (int ui = 0; ui < 2; ++ui) {
            int u = ns * 8 + 2 * a + ui;
            int b_row = bg * 128 + mt * 16 + (lane >> 2) + rs * 8;
            int j = hs * 16 + u;
            cs0[rs][ui] = c0in[b_row * 256 + j];
            cs1[rs][ui] = c0in[Bsz * NH + b_row * 256 + j];
        }

    float* outH = out + 2 * Bsz;
    int p = 0;
#pragma unroll 1
    for (int t = 0; t < Tst; ++t) {
        float acc[4][4];
#pragma unroll
        for (int g = 0; g < 4; ++g)
#pragma unroll
            for (int d = 0; d < 4; ++d) acc[g][d] = 0.f;

        // ---- L0: x chunks + W0h*h0[p], depth-2 prefetch ----
        {
            AF cur = lda(g_Xfrag + xoff(t, bg, mt, 0), lane);
            AF nxt = lda(g_Xfrag + xoff(t, bg, mt, 1), lane);
            compute_chunk(acc, cur, smq, BLK_W0XH + 0, BLK_W0XL + 0, lane, ns);
            cur = nxt;
            nxt = lda(g_Hfrag + hoff(0, p, bg, mt, 0), lane);
            compute_chunk(acc, cur, smq, BLK_W0XH + 1, BLK_W0XL + 1, lane, ns);
#pragma unroll 1
            for (int c = 0; c < 16; ++c) {
                cur = nxt;
                if (c < 15) nxt = lda(g_Hfrag + hoff(0, p, bg, mt, c + 1), lane);
                compute_chunk(acc, cur, smq, BLK_W0HH + c, BLK_W0HL + c, lane, ns);
            }
        }
        epilogue(0, 1 - p, bg, mt, hs, lane, ns, acc, cs0, bias_s, (t == Tst - 1) ? outH : nullptr);
        bar_arrive(g_cntA, g_genA, bg);

        bar_wait(g_genB, bg, (unsigned)t);   // h1[p] from step t-1 visible

#pragma unroll
        for (int g = 0; g < 4; ++g)
#pragma unroll
            for (int d = 0; d < 4; ++d) acc[g][d] = 0.f;

        // ---- L1 part A: W1h*h1[p] ----
        {
            AF cur = lda(g_Hfrag + hoff(1, p, bg, mt, 0), lane);
            AF nxt = cur;
#pragma unroll 1
            for (int c = 0; c < 16; ++c) {
                if (c < 15) nxt = lda(g_Hfrag + hoff(1, p, bg, mt, c + 1), lane);
                compute_chunk(acc, cur, smq, BLK_W1HH + c, BLK_W1HL + c, lane, ns);
                cur = nxt;
            }
        }
        bar_wait(g_genA, bg, (unsigned)(t + 1));  // everyone's h0[1-p]

        // ---- L1 part B: W1x*h0[1-p] ----
        {
            AF cur = lda(g_Hfrag + hoff(0, 1 - p, bg, mt, 0), lane);
            AF nxt = cur;
#pragma unroll 1
            for (int c = 0; c < 16; ++c) {
                if (c < 15) nxt = lda(g_Hfrag + hoff(0, 1 - p, bg, mt, c + 1), lane);
                compute_chunk(acc, cur, smq, BLK_W1XH + c, BLK_W1XL + c, lane, ns);
                cur = nxt;
            }
        }
        epilogue(1, 1 - p, bg, mt, hs, lane, ns, acc, cs1, bias_s, (t == Tst - 1) ? outH : nullptr);
        bar_arrive(g_cntB, g_genB, bg);
        p ^= 1;
    }

    float* outC = out + 2 * Bsz + 2 * Bsz * NH;
#pragma unroll
    for (int rs = 0; rs < 2; ++rs)
#pragma unroll
        for (int ui = 0; ui < 2; ++ui) {
            int u = ns * 8 + 2 * a + ui;
            int b_row = bg * 128 + mt * 16 + (lane >> 2) + rs * 8;
            int j = hs * 16 + u;
            outC[b_row * 256 + j] = cs0[rs][ui];
            outC[Bsz * NH + b_row * 256 + j] = cs1[rs][ui];
        }
}

// -------------------- decoded head --------------------
__global__ void decode_kernel(const float* __restrict__ fcw, const float* __restrict__ fcb,
                              const float* __restrict__ decw, const float* __restrict__ decb,
                              float* __restrict__ out) {
    int b = blockIdx.x * blockDim.x + threadIdx.x;
    if (b >= Bsz) return;
    const float* h1 = out + 2 * Bsz + Bsz * NH + b * 256;
    float d0 = decb[0], d1 = decb[1];
#pragma unroll 1
    for (int m = 0; m < 10; ++m) {
        float s = fcb[m];
        for (int j = 0; j < 256; ++j) s = fmaf(h1[j], fcw[m * 256 + j], s);
        s = fmaxf(s, 0.f);
        d0 = fmaf(s, decw[m], d0);
        d1 = fmaf(s, decw[10 + m], d1);
    }
    out[b] = d0;
    out[Bsz + b] = d1;
}

// -------------------- launch --------------------
extern "C" void kernel_launch(void* const* d_in, const int* in_sizes, int n_in,
                              void* d_out, int out_size) {
    const int*   input = (const int*)  d_in[0];
    const float* h0    = (const float*)d_in[1];
    const float* emb   = (const float*)d_in[3];
    const float* fcw   = (const float*)d_in[4];
    const float* fcb   = (const float*)d_in[5];
    const float* decw  = (const float*)d_in[6];
    const float* decb  = (const float*)d_in[7];
    float* out = (float*)d_out;

    cudaFuncSetAttribute(lstm_kernel, cudaFuncAttributeMaxDynamicSharedMemorySize, SMEM_SZ);

    unsigned nX = Tst * NBG * 8 * 2 * 32;
    pack_x_kernel<<<(nX + 255) / 256, 256>>>(input, emb);
    int nW = NGS * NBLK * 512 + 2048;
    prep_w_kernel<<<(nW + 255) / 256, 256>>>(
        (const float*)d_in[8], (const float*)d_in[9], (const float*)d_in[10], (const float*)d_in[11],
        (const float*)d_in[12], (const float*)d_in[13], (const float*)d_in[14], (const float*)d_in[15]);
    unsigned nH = 2 * NBG * 8 * 16 * 32;
    init_h_kernel<<<(nH + 255) / 256, 256>>>(h0);
    lstm_kernel<<<NCTA, 512, SMEM_SZ>>>(h0, (const float*)d_in[2], out);
    decode_kernel<<<(Bsz + 255) / 256, 256>>>(fcw, fcb, decw, decb, out);
}

// round 13
// speedup vs baseline: 2.3519x; 1.0422x over previous
#include <cuda_runtime.h>
#include <cuda_bf16.h>

#define Bsz 1024
#define Tst 300
#define NH  256
#define NBG 8      // batch groups (128 rows)
#define NGS 16     // gate-slice CTAs per group (64 gate cols each)
#define NCTA 128

#define BLK_W0XH 0
#define BLK_W0XL 2
#define BLK_W0HH 4
#define BLK_W0HL 20
#define BLK_W1XH 36
#define BLK_W1XL 52
#define BLK_W1HH 68
#define BLK_W1HL 84
#define NBLK     100
#define SMEM_SZ  (NBLK * 2048 + 512)

// -------------------- device scratch --------------------
__device__ unsigned g_Wfrag[(size_t)NGS * NBLK * 512];
__device__ float    g_biasP[2 * NGS * 64];
__device__ unsigned g_Xfrag[(size_t)Tst * NBG * 8 * 2 * 256];
__device__ unsigned g_Hfrag[2 * 2 * NBG * 8 * 16 * 256];
__device__ unsigned g_cntA[NBG], g_genA[NBG];
__device__ unsigned g_cntB[NBG], g_genB[NBG];

__device__ __forceinline__ size_t hoff(int l, int buf, int bg, int mt, int ch) {
    return ((((((size_t)(l * 2 + buf)) * NBG + bg) * 8 + mt) * 16 + ch) * 256);
}
__device__ __forceinline__ size_t xoff(int t, int bg, int mt, int c) {
    return ((((size_t)t * NBG + bg) * 8 + mt) * 2 + c) * 256;
}

__device__ __forceinline__ void split2(float v0, float v1, unsigned& hi, unsigned& lo) {
    __nv_bfloat16 h0 = __float2bfloat16(v0), h1 = __float2bfloat16(v1);
    __nv_bfloat16 l0 = __float2bfloat16(v0 - __bfloat162float(h0));
    __nv_bfloat16 l1 = __float2bfloat16(v1 - __bfloat162float(h1));
    hi = (unsigned)__bfloat16_as_ushort(h0) | ((unsigned)__bfloat16_as_ushort(h1) << 16);
    lo = (unsigned)__bfloat16_as_ushort(l0) | ((unsigned)__bfloat16_as_ushort(l1) << 16);
}
__device__ __forceinline__ float sigm(float x) { return 1.f / (1.f + __expf(-x)); }
__device__ __forceinline__ float tanh_f(float x) {
    x = fminf(fmaxf(x, -15.f), 15.f);
    float e = __expf(2.f * x);
    return __fdividef(e - 1.f, e + 1.f);
}

__device__ __forceinline__ void mma4(float* d, const unsigned* a, unsigned b0, unsigned b1) {
    asm volatile("mma.sync.aligned.m16n8k16.row.col.f32.bf16.bf16.f32 "
        "{%0,%1,%2,%3}, {%4,%5,%6,%7}, {%8,%9}, {%0,%1,%2,%3};"
        : "+f"(d[0]), "+f"(d[1]), "+f"(d[2]), "+f"(d[3])
        : "r"(a[0]), "r"(a[1]), "r"(a[2]), "r"(a[3]), "r"(b0), "r"(b1));
}

// -------------------- x gather --------------------
__device__ __forceinline__ float fetch_x(const int* __restrict__ input,
                                         const float* __restrict__ emb,
                                         int t, int b, int k) {
    if (k >= 25) return 0.f;
    long flat = (long)t * (Bsz * 25) + b * 25 + k;
    int s = (int)(flat / (Bsz * 300));
    int rr = (int)(flat % (Bsz * 300));
    int bb = rr / 300, e = rr % 300;
    return emb[(long)input[bb * 25 + s] * 300 + e];
}

// -------------------- prep kernels (layouts unchanged from R12) ------------
__global__ void pack_x_kernel(const int* __restrict__ input, const float* __restrict__ emb) {
    unsigned idx = blockIdx.x * blockDim.x + threadIdx.x;
    if (idx >= (unsigned)Tst * NBG * 8 * 2 * 32) return;
    int lane = idx & 31;
    unsigned r = idx >> 5;
    int c = r & 1; r >>= 1;
    int mt = r & 7; r >>= 3;
    int bg = r & 7;
    int t = r >> 3;
    unsigned ohi[4], olo[4];
#pragma unroll
    for (int reg = 0; reg < 4; ++reg) {
        int row = mt * 16 + (lane >> 2) + (reg & 1) * 8;
        int b = bg * 128 + row;
        int k = c * 16 + ((reg >> 1) & 1) * 8 + 2 * (lane & 3);
        float v0 = fetch_x(input, emb, t, b, k);
        float v1 = fetch_x(input, emb, t, b, k + 1);
        split2(v0, v1, ohi[reg], olo[reg]);
    }
    unsigned* base = g_Xfrag + (size_t)(idx >> 5) * 256;
    *(uint4*)(base + lane * 4)       = make_uint4(ohi[0], ohi[1], ohi[2], ohi[3]);
    *(uint4*)(base + 128 + lane * 4) = make_uint4(olo[0], olo[1], olo[2], olo[3]);
}

__global__ void prep_w_kernel(
    const float* __restrict__ Wih0, const float* __restrict__ Whh0,
    const float* __restrict__ bih0, const float* __restrict__ bhh0,
    const float* __restrict__ Wih1, const float* __restrict__ Whh1,
    const float* __restrict__ bih1, const float* __restrict__ bhh1) {
    const int NWF = NGS * NBLK * 512;
    int idx = blockIdx.x * blockDim.x + threadIdx.x;
    if (idx < NWF) {
        int hs = idx / (NBLK * 512);
        int rem = idx % (NBLK * 512);
        int blk = rem / 512, q = rem % 512;
        int ns = q >> 8, k2 = (q >> 7) & 1, L = (q >> 2) & 31, m = q & 3;
        int g = k2 * 2 + (m >> 1), regb = m & 1;
        int nt = g * 2 + ns;
        int mat, ch, hl;
        if (blk < 4) { mat = 0; hl = blk >> 1; ch = blk & 1; }
        else { int bb = blk - 4; mat = 1 + bb / 32; int cc = bb % 32; hl = cc >> 4; ch = cc & 15; }
        int k = ch * 16 + regb * 8 + 2 * (L & 3);
        int nl = nt * 8 + (L >> 2);
        int r = (nl >> 4) * 256 + hs * 16 + (nl & 15);
        float v0 = 0.f, v1 = 0.f;
        if (mat == 0) {
            if (k < 25)     v0 = Wih0[r * 25 + k];
            if (k + 1 < 25) v1 = Wih0[r * 25 + k + 1];
        } else if (mat == 1) { v0 = Whh0[r * 256 + k]; v1 = Whh0[r * 256 + k + 1]; }
        else if (mat == 2)   { v0 = Wih1[r * 256 + k]; v1 = Wih1[r * 256 + k + 1]; }
        else                 { v0 = Whh1[r * 256 + k]; v1 = Whh1[r * 256 + k + 1]; }
        unsigned hi, lo;
        split2(v0, v1, hi, lo);
        g_Wfrag[idx] = hl ? lo : hi;
    } else if (idx < NWF + 2048) {
        int i2 = idx - NWF;
        int l = i2 >> 10, rest = i2 & 1023, hs = rest >> 6, nl = rest & 63;
        int r = (nl >> 4) * 256 + hs * 16 + (nl & 15);
        g_biasP[i2] = (l == 0) ? (bih0[r] + bhh0[r]) : (bih1[r] + bhh1[r]);
    }
}

__global__ void init_h_kernel(const float* __restrict__ h0in) {
    unsigned idx = blockIdx.x * blockDim.x + threadIdx.x;
    if (idx < NBG) {
        g_cntA[idx] = 0; g_genA[idx] = 0;
        g_cntB[idx] = 0; g_genB[idx] = 0;
    }
    if (idx >= 2u * NBG * 8 * 16 * 32) return;
    int lane = idx & 31;
    unsigned r = idx >> 5;
    int ch = r & 15; r >>= 4;
    int mt = r & 7; r >>= 3;
    int bg = r & 7;
    int l = r >> 3;
    unsigned ohi[4], olo[4];
#pragma unroll
    for (int reg = 0; reg < 4; ++reg) {
        int row = mt * 16 + (lane >> 2) + (reg & 1) * 8;
        int b = bg * 128 + row;
        int j = ch * 16 + ((reg >> 1) & 1) * 8 + 2 * (lane & 3);
        const float* src = h0in + (size_t)l * (Bsz * NH) + b * 256 + j;
        split2(src[0], src[1], ohi[reg], olo[reg]);
    }
    unsigned* base = g_Hfrag + hoff(l, 0, bg, mt, ch);
    *(uint4*)(base + lane * 4)       = make_uint4(ohi[0], ohi[1], ohi[2], ohi[3]);
    *(uint4*)(base + 128 + lane * 4) = make_uint4(olo[0], olo[1], olo[2], olo[3]);
}

// -------------------- split group barrier --------------------
__device__ __forceinline__ void bar_arrive(unsigned* cnt, unsigned* gen, int grp) {
    __syncthreads();
    if (threadIdx.x == 0) {
        __threadfence();
        unsigned old = atomicAdd(&cnt[grp], 1u);
        if (old == NGS - 1) {
            atomicExch(&cnt[grp], 0u);
            __threadfence();
            atomicAdd(&gen[grp], 1u);
        }
    }
}
__device__ __forceinline__ void bar_wait(unsigned* gen, int grp, unsigned target) {
    if (threadIdx.x == 0) {
        volatile unsigned* gp = gen + grp;
        while (*gp < target) __nanosleep(32);
        __threadfence();
    }
    __syncthreads();
}

// -------------------- fragments --------------------
struct AF { unsigned h[4], l[4]; };
struct WF { unsigned b[16]; };   // wb (WH) in [0,8), wc (WL) in [8,16)

__device__ __forceinline__ AF lda(const unsigned* __restrict__ A, int lane) {
    AF f;
    uint4 a = __ldcg((const uint4*)(A + lane * 4));
    uint4 b = __ldcg((const uint4*)(A + 128 + lane * 4));
    f.h[0]=a.x; f.h[1]=a.y; f.h[2]=a.z; f.h[3]=a.w;
    f.l[0]=b.x; f.l[1]=b.y; f.l[2]=b.z; f.l[3]=b.w;
    return f;
}
__device__ __forceinline__ WF ldw(const uint4* __restrict__ smq, int blkh, int blkl,
                                  int lane, int ns) {
    WF w;
    const uint4* WH = smq + blkh * 128 + ns * 64;
    uint4 q0 = WH[lane], q1 = WH[32 + lane];
    const uint4* WL = smq + blkl * 128 + ns * 64;
    uint4 q2 = WL[lane], q3 = WL[32 + lane];
    w.b[0]=q0.x; w.b[1]=q0.y; w.b[2]=q0.z; w.b[3]=q0.w;
    w.b[4]=q1.x; w.b[5]=q1.y; w.b[6]=q1.z; w.b[7]=q1.w;
    w.b[8]=q2.x; w.b[9]=q2.y; w.b[10]=q2.z; w.b[11]=q2.w;
    w.b[12]=q3.x; w.b[13]=q3.y; w.b[14]=q3.z; w.b[15]=q3.w;
    return w;
}
__device__ __forceinline__ void mma_chunk(float (&acc)[4][4], const AF& a, const WF& w) {
#pragma unroll
    for (int g = 0; g < 4; ++g) mma4(acc[g], a.h, w.b[2*g], w.b[2*g+1]);
#pragma unroll
    for (int g = 0; g < 4; ++g) mma4(acc[g], a.l, w.b[2*g], w.b[2*g+1]);
#pragma unroll
    for (int g = 0; g < 4; ++g) mma4(acc[g], a.h, w.b[8+2*g], w.b[8+2*g+1]);
}

// -------------------- epilogue --------------------
__device__ __forceinline__ void epilogue(int l, int pnew, int bg, int mt, int hs,
        int lane, int ns,
        float (&acc)[4][4], float (&cs)[2][2], const float* __restrict__ bias_s,
        float* __restrict__ outH) {
    int a = lane & 3;
    unsigned* base = g_Hfrag + hoff(l, pnew, bg, mt, hs);
    int lanep = (lane >> 2) * 4 + a;
#pragma unroll
    for (int rs = 0; rs < 2; ++rs) {
        float hv[2];
#pragma unroll
        for (int ui = 0; ui < 2; ++ui) {
            int u = ns * 8 + 2 * a + ui;
            int dr = rs * 2 + ui;
            float gi = acc[0][dr] + bias_s[l * 64 + u];
            float gf = acc[1][dr] + bias_s[l * 64 + 16 + u];
            float gg = acc[2][dr] + bias_s[l * 64 + 32 + u];
            float go = acc[3][dr] + bias_s[l * 64 + 48 + u];
            float c = fmaf(sigm(gf), cs[rs][ui], sigm(gi) * tanh_f(gg));
            cs[rs][ui] = c;
            hv[ui] = sigm(go) * tanh_f(c);
        }
        unsigned hi, lo;
        split2(hv[0], hv[1], hi, lo);
        base[lanep * 4 + rs + 2 * ns]       = hi;
        base[128 + lanep * 4 + rs + 2 * ns] = lo;
        if (outH) {
            int b_row = bg * 128 + mt * 16 + (lane >> 2) + rs * 8;
#pragma unroll
            for (int ui = 0; ui < 2; ++ui)
                outH[(size_t)l * Bsz * NH + b_row * 256 + hs * 16 + ns * 8 + 2 * a + ui] = hv[ui];
        }
    }
}

// -------------------- main persistent kernel --------------------
// 128 CTAs x 512 threads. Warp (mt, ns): 16 rows x 32 gate cols.
// R13: rolling W register prefetch + phase-boundary A prefetch + waitB hoist
//      + L1B rotated to start at own chunk (ch = hs).
__global__ void __launch_bounds__(512, 1) lstm_kernel(
    const float* __restrict__ h0in, const float* __restrict__ c0in,
    float* __restrict__ out) {
    extern __shared__ uint4 smq[];
    const int tid = threadIdx.x, lane = tid & 31, wid = tid >> 5;
    const int mt = wid & 7;
    const int ns = wid >> 3;
    const int bg = blockIdx.x >> 4;
    const int hs = blockIdx.x & 15;
    const int a = lane & 3;

    const uint4* wsrc = (const uint4*)g_Wfrag + (size_t)hs * (NBLK * 128);
    for (int i = tid; i < NBLK * 128; i += 512) smq[i] = wsrc[i];
    float* bias_s = (float*)(smq + NBLK * 128);
    if (tid < 128) bias_s[tid] = g_biasP[(tid >> 6) * 1024 + hs * 64 + (tid & 63)];
    __syncthreads();

    float cs0[2][2], cs1[2][2];
#pragma unroll
    for (int rs = 0; rs < 2; ++rs)
#pragma unroll
        for (int ui = 0; ui < 2; ++ui) {
            int u = ns * 8 + 2 * a + ui;
            int b_row = bg * 128 + mt * 16 + (lane >> 2) + rs * 8;
            int j = hs * 16 + u;
            cs0[rs][ui] = c0in[b_row * 256 + j];
            cs1[rs][ui] = c0in[Bsz * NH + b_row * 256 + j];
        }

    float* outH = out + 2 * Bsz;
    int p = 0;
    // seed: prefetch x[0] chunk 0
    AF a_seed = lda(g_Xfrag + xoff(0, bg, mt, 0), lane);

#pragma unroll 1
    for (int t = 0; t < Tst; ++t) {
        float acc[4][4];
#pragma unroll
        for (int g = 0; g < 4; ++g)
#pragma unroll
            for (int d = 0; d < 4; ++d) acc[g][d] = 0.f;

        // ================= L0: x(2 chunks) + W0h*h0[p](16 chunks) ==========
        {
            AF a_cur = a_seed;
            WF w_cur = ldw(smq, BLK_W0XH + 0, BLK_W0XL + 0, lane, ns);
            AF a_nxt = lda(g_Xfrag + xoff(t, bg, mt, 1), lane);
            WF w_nxt = ldw(smq, BLK_W0XH + 1, BLK_W0XL + 1, lane, ns);
            mma_chunk(acc, a_cur, w_cur);                       // x chunk 0
            a_cur = a_nxt; w_cur = w_nxt;
            a_nxt = lda(g_Hfrag + hoff(0, p, bg, mt, 0), lane);
            w_nxt = ldw(smq, BLK_W0HH + 0, BLK_W0HL + 0, lane, ns);
            mma_chunk(acc, a_cur, w_cur);                       // x chunk 1
#pragma unroll 1
            for (int c = 0; c < 16; ++c) {
                a_cur = a_nxt; w_cur = w_nxt;
                if (c < 15) {
                    a_nxt = lda(g_Hfrag + hoff(0, p, bg, mt, c + 1), lane);
                    w_nxt = ldw(smq, BLK_W0HH + c + 1, BLK_W0HL + c + 1, lane, ns);
                }
                mma_chunk(acc, a_cur, w_cur);
            }
        }
        // waitB hoisted: h1[p] (written step t-1) must be visible before L1A;
        // waiting here lets the L1A chunk-0 prefetch overlap the L0 epilogue.
        bar_wait(g_genB, bg, (unsigned)t);
        a_seed = lda(g_Hfrag + hoff(1, p, bg, mt, 0), lane);    // L1A chunk 0

        epilogue(0, 1 - p, bg, mt, hs, lane, ns, acc, cs0, bias_s,
                 (t == Tst - 1) ? outH : nullptr);
        bar_arrive(g_cntA, g_genA, bg);

#pragma unroll
        for (int g = 0; g < 4; ++g)
#pragma unroll
            for (int d = 0; d < 4; ++d) acc[g][d] = 0.f;

        // ================= L1 part A: W1h*h1[p] ============================
        {
            AF a_cur = a_seed;
            WF w_cur = ldw(smq, BLK_W1HH + 0, BLK_W1HL + 0, lane, ns);
            AF a_nxt = a_cur; WF w_nxt = w_cur;
#pragma unroll 1
            for (int c = 0; c < 16; ++c) {
                if (c < 15) {
                    a_nxt = lda(g_Hfrag + hoff(1, p, bg, mt, c + 1), lane);
                    w_nxt = ldw(smq, BLK_W1HH + c + 1, BLK_W1HL + c + 1, lane, ns);
                }
                mma_chunk(acc, a_cur, w_cur);
                a_cur = a_nxt; w_cur = w_nxt;
            }
        }
        // Prefetch L1B's own chunk (ch = hs): this CTA wrote those columns in
        // its L0 epilogue (synced by arrive's __syncthreads + fence), so it's
        // legal to read before the group-wide waitA.
        a_seed = lda(g_Hfrag + hoff(0, 1 - p, bg, mt, hs), lane);
        bar_wait(g_genA, bg, (unsigned)(t + 1));

        // ================= L1 part B: W1x*h0[1-p], rotated from ch=hs =======
        {
            AF a_cur = a_seed;
            WF w_cur = ldw(smq, BLK_W1XH + hs, BLK_W1XL + hs, lane, ns);
            AF a_nxt = a_cur; WF w_nxt = w_cur;
#pragma unroll 1
            for (int i = 0; i < 16; ++i) {
                if (i < 15) {
                    int ch2 = (hs + i + 1) & 15;
                    a_nxt = lda(g_Hfrag + hoff(0, 1 - p, bg, mt, ch2), lane);
                    w_nxt = ldw(smq, BLK_W1XH + ch2, BLK_W1XL + ch2, lane, ns);
                }
                mma_chunk(acc, a_cur, w_cur);
                a_cur = a_nxt; w_cur = w_nxt;
            }
        }
        // Prefetch next step's x chunk 0 (static data, always safe).
        {
            int tt = (t + 1 < Tst) ? t + 1 : 0;
            a_seed = lda(g_Xfrag + xoff(tt, bg, mt, 0), lane);
        }
        epilogue(1, 1 - p, bg, mt, hs, lane, ns, acc, cs1, bias_s,
                 (t == Tst - 1) ? outH : nullptr);
        bar_arrive(g_cntB, g_genB, bg);
        p ^= 1;
    }

    float* outC = out + 2 * Bsz + 2 * Bsz * NH;
#pragma unroll
    for (int rs = 0; rs < 2; ++rs)
#pragma unroll
        for (int ui = 0; ui < 2; ++ui) {
            int u = ns * 8 + 2 * a + ui;
            int b_row = bg * 128 + mt * 16 + (lane >> 2) + rs * 8;
            int j = hs * 16 + u;
            outC[b_row * 256 + j] = cs0[rs][ui];
            outC[Bsz * NH + b_row * 256 + j] = cs1[rs][ui];
        }
}

// -------------------- decoded head --------------------
__global__ void decode_kernel(const float* __restrict__ fcw, const float* __restrict__ fcb,
                              const float* __restrict__ decw, const float* __restrict__ decb,
                              float* __restrict__ out) {
    int b = blockIdx.x * blockDim.x + threadIdx.x;
    if (b >= Bsz) return;
    const float* h1 = out + 2 * Bsz + Bsz * NH + b * 256;
    float d0 = decb[0], d1 = decb[1];
#pragma unroll 1
    for (int m = 0; m < 10; ++m) {
        float s = fcb[m];
        for (int j = 0; j < 256; ++j) s = fmaf(h1[j], fcw[m * 256 + j], s);
        s = fmaxf(s, 0.f);
        d0 = fmaf(s, decw[m], d0);
        d1 = fmaf(s, decw[10 + m], d1);
    }
    out[b] = d0;
    out[Bsz + b] = d1;
}

// -------------------- launch --------------------
extern "C" void kernel_launch(void* const* d_in, const int* in_sizes, int n_in,
                              void* d_out, int out_size) {
    const int*   input = (const int*)  d_in[0];
    const float* h0    = (const float*)d_in[1];
    const float* emb   = (const float*)d_in[3];
    const float* fcw   = (const float*)d_in[4];
    const float* fcb   = (const float*)d_in[5];
    const float* decw  = (const float*)d_in[6];
    const float* decb  = (const float*)d_in[7];
    float* out = (float*)d_out;

    cudaFuncSetAttribute(lstm_kernel, cudaFuncAttributeMaxDynamicSharedMemorySize, SMEM_SZ);

    unsigned nX = Tst * NBG * 8 * 2 * 32;
    pack_x_kernel<<<(nX + 255) / 256, 256>>>(input, emb);
    int nW = NGS * NBLK * 512 + 2048;
    prep_w_kernel<<<(nW + 255) / 256, 256>>>(
        (const float*)d_in[8], (const float*)d_in[9], (const float*)d_in[10], (const float*)d_in[11],
        (const float*)d_in[12], (const float*)d_in[13], (const float*)d_in[14], (const float*)d_in[15]);
    unsigned nH = 2 * NBG * 8 * 16 * 32;
    init_h_kernel<<<(nH + 255) / 256, 256>>>(h0);
    lstm_kernel<<<NCTA, 512, SMEM_SZ>>>(h0, (const float*)d_in[2], out);
    decode_kernel<<<(Bsz + 255) / 256, 256>>>(fcw, fcb, decw, decb, out);
}

// round 14
// speedup vs baseline: 2.6681x; 1.1344x over previous
#include <cuda_runtime.h>
#include <cuda_fp16.h>

#define Bsz 1024
#define Tst 300
#define NH  256
#define NBG 8      // batch groups (128 rows)
#define NGS 16     // gate-slice CTAs per group (64 gate cols each)
#define NCTA 128

#define BLK_W0XH 0
#define BLK_W0XL 2
#define BLK_W0HH 4
#define BLK_W0HL 20
#define BLK_W1XH 36
#define BLK_W1XL 52
#define BLK_W1HH 68
#define BLK_W1HL 84
#define NBLK     100
#define SMEM_SZ  (NBLK * 2048 + 512)

// -------------------- device scratch --------------------
__device__ unsigned g_Wfrag[(size_t)NGS * NBLK * 512];        // fp16 hi/lo W fragments
__device__ float    g_biasP[2 * NGS * 64];
__device__ unsigned g_Xfrag[(size_t)Tst * NBG * 8 * 2 * 128]; // fp16 A fragments (20 MB)
__device__ unsigned g_Hfrag[2 * 2 * NBG * 8 * 16 * 128];      // fp16 h fragments (2 MB)
__device__ unsigned g_cntA[NBG], g_genA[NBG];
__device__ unsigned g_cntB[NBG], g_genB[NBG];

__device__ __forceinline__ size_t hoff(int l, int buf, int bg, int mt, int ch) {
    return ((((((size_t)(l * 2 + buf)) * NBG + bg) * 8 + mt) * 16 + ch) * 128);
}
__device__ __forceinline__ size_t xoff(int t, int bg, int mt, int c) {
    return ((((size_t)t * NBG + bg) * 8 + mt) * 2 + c) * 128;
}

__device__ __forceinline__ unsigned pack_h2(float v0, float v1) {
    __half2 h = __floats2half2_rn(v0, v1);
    return *(unsigned*)&h;
}
__device__ __forceinline__ void splitw2(float v0, float v1, unsigned& hi, unsigned& lo) {
    __half h0 = __float2half_rn(v0), h1 = __float2half_rn(v1);
    __half l0 = __float2half_rn(v0 - __half2float(h0));
    __half l1 = __float2half_rn(v1 - __half2float(h1));
    hi = (unsigned)*(unsigned short*)&h0 | ((unsigned)*(unsigned short*)&h1 << 16);
    lo = (unsigned)*(unsigned short*)&l0 | ((unsigned)*(unsigned short*)&l1 << 16);
}
__device__ __forceinline__ float sigm(float x) { return 1.f / (1.f + __expf(-x)); }
__device__ __forceinline__ float tanh_f(float x) {
    x = fminf(fmaxf(x, -15.f), 15.f);
    float e = __expf(2.f * x);
    return __fdividef(e - 1.f, e + 1.f);
}

__device__ __forceinline__ void mma4(float* d, const unsigned* a, unsigned b0, unsigned b1) {
    asm volatile("mma.sync.aligned.m16n8k16.row.col.f32.f16.f16.f32 "
        "{%0,%1,%2,%3}, {%4,%5,%6,%7}, {%8,%9}, {%0,%1,%2,%3};"
        : "+f"(d[0]), "+f"(d[1]), "+f"(d[2]), "+f"(d[3])
        : "r"(a[0]), "r"(a[1]), "r"(a[2]), "r"(a[3]), "r"(b0), "r"(b1));
}

// -------------------- x gather --------------------
__device__ __forceinline__ float fetch_x(const int* __restrict__ input,
                                         const float* __restrict__ emb,
                                         int t, int b, int k) {
    if (k >= 25) return 0.f;
    long flat = (long)t * (Bsz * 25) + b * 25 + k;
    int s = (int)(flat / (Bsz * 300));
    int rr = (int)(flat % (Bsz * 300));
    int bb = rr / 300, e = rr % 300;
    return emb[(long)input[bb * 25 + s] * 300 + e];
}

// -------------------- prep kernels --------------------
__global__ void pack_x_kernel(const int* __restrict__ input, const float* __restrict__ emb) {
    unsigned idx = blockIdx.x * blockDim.x + threadIdx.x;
    if (idx >= (unsigned)Tst * NBG * 8 * 2 * 32) return;
    int lane = idx & 31;
    unsigned r = idx >> 5;
    int c = r & 1; r >>= 1;
    int mt = r & 7; r >>= 3;
    int bg = r & 7;
    int t = r >> 3;
    unsigned oh[4];
#pragma unroll
    for (int reg = 0; reg < 4; ++reg) {
        int row = mt * 16 + (lane >> 2) + (reg & 1) * 8;
        int b = bg * 128 + row;
        int k = c * 16 + ((reg >> 1) & 1) * 8 + 2 * (lane & 3);
        oh[reg] = pack_h2(fetch_x(input, emb, t, b, k),
                          fetch_x(input, emb, t, b, k + 1));
    }
    unsigned* base = g_Xfrag + (size_t)(idx >> 5) * 128;
    *(uint4*)(base + lane * 4) = make_uint4(oh[0], oh[1], oh[2], oh[3]);
}

__global__ void prep_w_kernel(
    const float* __restrict__ Wih0, const float* __restrict__ Whh0,
    const float* __restrict__ bih0, const float* __restrict__ bhh0,
    const float* __restrict__ Wih1, const float* __restrict__ Whh1,
    const float* __restrict__ bih1, const float* __restrict__ bhh1) {
    const int NWF = NGS * NBLK * 512;
    int idx = blockIdx.x * blockDim.x + threadIdx.x;
    if (idx < NWF) {
        int hs = idx / (NBLK * 512);
        int rem = idx % (NBLK * 512);
        int blk = rem / 512, q = rem % 512;
        int ns = q >> 8, k2 = (q >> 7) & 1, L = (q >> 2) & 31, m = q & 3;
        int g = k2 * 2 + (m >> 1), regb = m & 1;
        int nt = g * 2 + ns;
        int mat, ch, hl;
        if (blk < 4) { mat = 0; hl = blk >> 1; ch = blk & 1; }
        else { int bb = blk - 4; mat = 1 + bb / 32; int cc = bb % 32; hl = cc >> 4; ch = cc & 15; }
        int k = ch * 16 + regb * 8 + 2 * (L & 3);
        int nl = nt * 8 + (L >> 2);
        int r = (nl >> 4) * 256 + hs * 16 + (nl & 15);
        float v0 = 0.f, v1 = 0.f;
        if (mat == 0) {
            if (k < 25)     v0 = Wih0[r * 25 + k];
            if (k + 1 < 25) v1 = Wih0[r * 25 + k + 1];
        } else if (mat == 1) { v0 = Whh0[r * 256 + k]; v1 = Whh0[r * 256 + k + 1]; }
        else if (mat == 2)   { v0 = Wih1[r * 256 + k]; v1 = Wih1[r * 256 + k + 1]; }
        else                 { v0 = Whh1[r * 256 + k]; v1 = Whh1[r * 256 + k + 1]; }
        unsigned hi, lo;
        splitw2(v0, v1, hi, lo);
        g_Wfrag[idx] = hl ? lo : hi;
    } else if (idx < NWF + 2048) {
        int i2 = idx - NWF;
        int l = i2 >> 10, rest = i2 & 1023, hs = rest >> 6, nl = rest & 63;
        int r = (nl >> 4) * 256 + hs * 16 + (nl & 15);
        g_biasP[i2] = (l == 0) ? (bih0[r] + bhh0[r]) : (bih1[r] + bhh1[r]);
    }
}

__global__ void init_h_kernel(const float* __restrict__ h0in) {
    unsigned idx = blockIdx.x * blockDim.x + threadIdx.x;
    if (idx < NBG) {
        g_cntA[idx] = 0; g_genA[idx] = 0;
        g_cntB[idx] = 0; g_genB[idx] = 0;
    }
    if (idx >= 2u * NBG * 8 * 16 * 32) return;
    int lane = idx & 31;
    unsigned r = idx >> 5;
    int ch = r & 15; r >>= 4;
    int mt = r & 7; r >>= 3;
    int bg = r & 7;
    int l = r >> 3;
    unsigned oh[4];
#pragma unroll
    for (int reg = 0; reg < 4; ++reg) {
        int row = mt * 16 + (lane >> 2) + (reg & 1) * 8;
        int b = bg * 128 + row;
        int j = ch * 16 + ((reg >> 1) & 1) * 8 + 2 * (lane & 3);
        const float* src = h0in + (size_t)l * (Bsz * NH) + b * 256 + j;
        oh[reg] = pack_h2(src[0], src[1]);
    }
    unsigned* base = g_Hfrag + hoff(l, 0, bg, mt, ch);
    *(uint4*)(base + lane * 4) = make_uint4(oh[0], oh[1], oh[2], oh[3]);
}

// -------------------- split group barrier --------------------
__device__ __forceinline__ void bar_arrive(unsigned* cnt, unsigned* gen, int grp) {
    __syncthreads();
    if (threadIdx.x == 0) {
        __threadfence();
        unsigned old = atomicAdd(&cnt[grp], 1u);
        if (old == NGS - 1) {
            atomicExch(&cnt[grp], 0u);
            __threadfence();
            atomicAdd(&gen[grp], 1u);
        }
    }
}
__device__ __forceinline__ void bar_wait(unsigned* gen, int grp, unsigned target) {
    if (threadIdx.x == 0) {
        volatile unsigned* gp = gen + grp;
        while (*gp < target) __nanosleep(32);
        __threadfence();
    }
    __syncthreads();
}

// -------------------- fragments --------------------
struct AF { unsigned h[4]; };
struct WF { unsigned b[16]; };   // Whi in [0,8), Wlo in [8,16)

__device__ __forceinline__ AF lda(const unsigned* __restrict__ A, int lane) {
    AF f;
    uint4 a = __ldcg((const uint4*)(A + lane * 4));
    f.h[0]=a.x; f.h[1]=a.y; f.h[2]=a.z; f.h[3]=a.w;
    return f;
}
__device__ __forceinline__ WF ldw(const uint4* __restrict__ smq, int blkh, int blkl,
                                  int lane, int ns) {
    WF w;
    const uint4* WH = smq + blkh * 128 + ns * 64;
    uint4 q0 = WH[lane], q1 = WH[32 + lane];
    const uint4* WL = smq + blkl * 128 + ns * 64;
    uint4 q2 = WL[lane], q3 = WL[32 + lane];
    w.b[0]=q0.x; w.b[1]=q0.y; w.b[2]=q0.z; w.b[3]=q0.w;
    w.b[4]=q1.x; w.b[5]=q1.y; w.b[6]=q1.z; w.b[7]=q1.w;
    w.b[8]=q2.x; w.b[9]=q2.y; w.b[10]=q2.z; w.b[11]=q2.w;
    w.b[12]=q3.x; w.b[13]=q3.y; w.b[14]=q3.z; w.b[15]=q3.w;
    return w;
}
__device__ __forceinline__ void mma_chunk(float (&acc)[4][4], const AF& a, const WF& w) {
#pragma unroll
    for (int g = 0; g < 4; ++g) mma4(acc[g], a.h, w.b[2*g], w.b[2*g+1]);
#pragma unroll
    for (int g = 0; g < 4; ++g) mma4(acc[g], a.h, w.b[8+2*g], w.b[8+2*g+1]);
}

// -------------------- epilogue --------------------
__device__ __forceinline__ void epilogue(int l, int pnew, int bg, int mt, int hs,
        int lane, int ns,
        float (&acc)[4][4], float (&cs)[2][2], const float* __restrict__ bias_s,
        float* __restrict__ outH) {
    int a = lane & 3;
    unsigned* base = g_Hfrag + hoff(l, pnew, bg, mt, hs);
    int lanep = (lane >> 2) * 4 + a;
#pragma unroll
    for (int rs = 0; rs < 2; ++rs) {
        float hv[2];
#pragma unroll
        for (int ui = 0; ui < 2; ++ui) {
            int u = ns * 8 + 2 * a + ui;
            int dr = rs * 2 + ui;
            float gi = acc[0][dr] + bias_s[l * 64 + u];
            float gf = acc[1][dr] + bias_s[l * 64 + 16 + u];
            float gg = acc[2][dr] + bias_s[l * 64 + 32 + u];
            float go = acc[3][dr] + bias_s[l * 64 + 48 + u];
            float c = fmaf(sigm(gf), cs[rs][ui], sigm(gi) * tanh_f(gg));
            cs[rs][ui] = c;
            hv[ui] = sigm(go) * tanh_f(c);
        }
        base[lanep * 4 + rs + 2 * ns] = pack_h2(hv[0], hv[1]);
        if (outH) {
            int b_row = bg * 128 + mt * 16 + (lane >> 2) + rs * 8;
#pragma unroll
            for (int ui = 0; ui < 2; ++ui)
                outH[(size_t)l * Bsz * NH + b_row * 256 + hs * 16 + ns * 8 + 2 * a + ui] = hv[ui];
        }
    }
}

// -------------------- main persistent kernel --------------------
// 128 CTAs x 512 threads. Warp (mt, ns): 16 rows x 32 gate cols.
// R14: fp16 2-term split (A rounded to fp16; W = Whi + Wlo) -> 8 MMA/chunk.
__global__ void __launch_bounds__(512, 1) lstm_kernel(
    const float* __restrict__ h0in, const float* __restrict__ c0in,
    float* __restrict__ out) {
    extern __shared__ uint4 smq[];
    const int tid = threadIdx.x, lane = tid & 31, wid = tid >> 5;
    const int mt = wid & 7;
    const int ns = wid >> 3;
    const int bg = blockIdx.x >> 4;
    const int hs = blockIdx.x & 15;
    const int a = lane & 3;

    const uint4* wsrc = (const uint4*)g_Wfrag + (size_t)hs * (NBLK * 128);
    for (int i = tid; i < NBLK * 128; i += 512) smq[i] = wsrc[i];
    float* bias_s = (float*)(smq + NBLK * 128);
    if (tid < 128) bias_s[tid] = g_biasP[(tid >> 6) * 1024 + hs * 64 + (tid & 63)];
    __syncthreads();

    float cs0[2][2], cs1[2][2];
#pragma unroll
    for (int rs = 0; rs < 2; ++rs)
#pragma unroll
        for (int ui = 0; ui < 2; ++ui) {
            int u = ns * 8 + 2 * a + ui;
            int b_row = bg * 128 + mt * 16 + (lane >> 2) + rs * 8;
            int j = hs * 16 + u;
            cs0[rs][ui] = c0in[b_row * 256 + j];
            cs1[rs][ui] = c0in[Bsz * NH + b_row * 256 + j];
        }

    float* outH = out + 2 * Bsz;
    int p = 0;
    AF a_seed = lda(g_Xfrag + xoff(0, bg, mt, 0), lane);

#pragma unroll 1
    for (int t = 0; t < Tst; ++t) {
        float acc[4][4];
#pragma unroll
        for (int g = 0; g < 4; ++g)
#pragma unroll
            for (int d = 0; d < 4; ++d) acc[g][d] = 0.f;

        // ================= L0: x(2 chunks) + W0h*h0[p](16 chunks) ==========
        {
            AF a_cur = a_seed;
            WF w_cur = ldw(smq, BLK_W0XH + 0, BLK_W0XL + 0, lane, ns);
            AF a_nxt = lda(g_Xfrag + xoff(t, bg, mt, 1), lane);
            WF w_nxt = ldw(smq, BLK_W0XH + 1, BLK_W0XL + 1, lane, ns);
            mma_chunk(acc, a_cur, w_cur);
            a_cur = a_nxt; w_cur = w_nxt;
            a_nxt = lda(g_Hfrag + hoff(0, p, bg, mt, 0), lane);
            w_nxt = ldw(smq, BLK_W0HH + 0, BLK_W0HL + 0, lane, ns);
            mma_chunk(acc, a_cur, w_cur);
#pragma unroll 1
            for (int c = 0; c < 16; ++c) {
                a_cur = a_nxt; w_cur = w_nxt;
                if (c < 15) {
                    a_nxt = lda(g_Hfrag + hoff(0, p, bg, mt, c + 1), lane);
                    w_nxt = ldw(smq, BLK_W0HH + c + 1, BLK_W0HL + c + 1, lane, ns);
                }
                mma_chunk(acc, a_cur, w_cur);
            }
        }
        bar_wait(g_genB, bg, (unsigned)t);
        a_seed = lda(g_Hfrag + hoff(1, p, bg, mt, 0), lane);

        epilogue(0, 1 - p, bg, mt, hs, lane, ns, acc, cs0, bias_s,
                 (t == Tst - 1) ? outH : nullptr);
        bar_arrive(g_cntA, g_genA, bg);

#pragma unroll
        for (int g = 0; g < 4; ++g)
#pragma unroll
            for (int d = 0; d < 4; ++d) acc[g][d] = 0.f;

        // ================= L1 part A: W1h*h1[p] ============================
        {
            AF a_cur = a_seed;
            WF w_cur = ldw(smq, BLK_W1HH + 0, BLK_W1HL + 0, lane, ns);
            AF a_nxt = a_cur; WF w_nxt = w_cur;
#pragma unroll 1
            for (int c = 0; c < 16; ++c) {
                if (c < 15) {
                    a_nxt = lda(g_Hfrag + hoff(1, p, bg, mt, c + 1), lane);
                    w_nxt = ldw(smq, BLK_W1HH + c + 1, BLK_W1HL + c + 1, lane, ns);
                }
                mma_chunk(acc, a_cur, w_cur);
                a_cur = a_nxt; w_cur = w_nxt;
            }
        }
        a_seed = lda(g_Hfrag + hoff(0, 1 - p, bg, mt, hs), lane);   // own chunk, legal pre-wait
        bar_wait(g_genA, bg, (unsigned)(t + 1));

        // ================= L1 part B: W1x*h0[1-p], rotated from ch=hs =======
        {
            AF a_cur = a_seed;
            WF w_cur = ldw(smq, BLK_W1XH + hs, BLK_W1XL + hs, lane, ns);
            AF a_nxt = a_cur; WF w_nxt = w_cur;
#pragma unroll 1
            for (int i = 0; i < 16; ++i) {
                if (i < 15) {
                    int ch2 = (hs + i + 1) & 15;
                    a_nxt = lda(g_Hfrag + hoff(0, 1 - p, bg, mt, ch2), lane);
                    w_nxt = ldw(smq, BLK_W1XH + ch2, BLK_W1XL + ch2, lane, ns);
                }
                mma_chunk(acc, a_cur, w_cur);
                a_cur = a_nxt; w_cur = w_nxt;
            }
        }
        {
            int tt = (t + 1 < Tst) ? t + 1 : 0;
            a_seed = lda(g_Xfrag + xoff(tt, bg, mt, 0), lane);
        }
        epilogue(1, 1 - p, bg, mt, hs, lane, ns, acc, cs1, bias_s,
                 (t == Tst - 1) ? outH : nullptr);
        bar_arrive(g_cntB, g_genB, bg);
        p ^= 1;
    }

    float* outC = out + 2 * Bsz + 2 * Bsz * NH;
#pragma unroll
    for (int rs = 0; rs < 2; ++rs)
#pragma unroll
        for (int ui = 0; ui < 2; ++ui) {
            int u = ns * 8 + 2 * a + ui;
            int b_row = bg * 128 + mt * 16 + (lane >> 2) + rs * 8;
            int j = hs * 16 + u;
            outC[b_row * 256 + j] = cs0[rs][ui];
            outC[Bsz * NH + b_row * 256 + j] = cs1[rs][ui];
        }
}

// -------------------- decoded head --------------------
__global__ void decode_kernel(const float* __restrict__ fcw, const float* __restrict__ fcb,
                              const float* __restrict__ decw, const float* __restrict__ decb,
                              float* __restrict__ out) {
    int b = blockIdx.x * blockDim.x + threadIdx.x;
    if (b >= Bsz) return;
    const float* h1 = out + 2 * Bsz + Bsz * NH + b * 256;
    float d0 = decb[0], d1 = decb[1];
#pragma unroll 1
    for (int m = 0; m < 10; ++m) {
        float s = fcb[m];
        for (int j = 0; j < 256; ++j) s = fmaf(h1[j], fcw[m * 256 + j], s);
        s = fmaxf(s, 0.f);
        d0 = fmaf(s, decw[m], d0);
        d1 = fmaf(s, decw[10 + m], d1);
    }
    out[b] = d0;
    out[Bsz + b] = d1;
}

// -------------------- launch --------------------
extern "C" void kernel_launch(void* const* d_in, const int* in_sizes, int n_in,
                              void* d_out, int out_size) {
    const int*   input = (const int*)  d_in[0];
    const float* h0    = (const float*)d_in[1];
    const float* emb   = (const float*)d_in[3];
    const float* fcw   = (const float*)d_in[4];
    const float* fcb   = (const float*)d_in[5];
    const float* decw  = (const float*)d_in[6];
    const float* decb  = (const float*)d_in[7];
    float* out = (float*)d_out;

    cudaFuncSetAttribute(lstm_kernel, cudaFuncAttributeMaxDynamicSharedMemorySize, SMEM_SZ);

    unsigned nX = Tst * NBG * 8 * 2 * 32;
    pack_x_kernel<<<(nX + 255) / 256, 256>>>(input, emb);
    int nW = NGS * NBLK * 512 + 2048;
    prep_w_kernel<<<(nW + 255) / 256, 256>>>(
        (const float*)d_in[8], (const float*)d_in[9], (const float*)d_in[10], (const float*)d_in[11],
        (const float*)d_in[12], (const float*)d_in[13], (const float*)d_in[14], (const float*)d_in[15]);
    unsigned nH = 2 * NBG * 8 * 16 * 32;
    init_h_kernel<<<(nH + 255) / 256, 256>>>(h0);
    lstm_kernel<<<NCTA, 512, SMEM_SZ>>>(h0, (const float*)d_in[2], out);
    decode_kernel<<<(Bsz + 255) / 256, 256>>>(fcw, fcb, decw, decb, out);
}